// round 13
// baseline (speedup 1.0000x reference)
#include <cuda_runtime.h>
#include <cuda_bf16.h>
#include <stdint.h>
#include <math.h>

#define BB 8
#define TT 256
#define DD 1024
#define LL 12
#define FF 4096
#define VV 32000
#define MM (BB*TT)   // 2048 rows

// ======================= scratch (static device globals; no runtime alloc) =======================
__device__ __align__(256) float g_h [MM*DD];
__device__ __align__(256) float g_r [MM*DD];
__device__ __align__(256) float g_k [MM*DD];
__device__ __align__(256) float g_v [MM*DD];
__device__ __align__(256) float g_st[MM*DD];
__device__ __align__(256) float g_g1[MM*FF];

__device__ __align__(256) __nv_bfloat16 g_xnh[MM*DD], g_xnl[MM*DD];
__device__ __align__(256) __nv_bfloat16 g_gh [MM*FF], g_gl [MM*FF];

__device__ __align__(256) __nv_bfloat16 g_wrh[LL*DD*DD], g_wrl[LL*DD*DD];
__device__ __align__(256) __nv_bfloat16 g_wkh[LL*DD*DD], g_wkl[LL*DD*DD];
__device__ __align__(256) __nv_bfloat16 g_wvh[LL*DD*DD], g_wvl[LL*DD*DD];
__device__ __align__(256) __nv_bfloat16 g_woh[LL*DD*DD], g_wol[LL*DD*DD];
__device__ __align__(256) __nv_bfloat16 g_w1h[LL*FF*DD], g_w1l[LL*FF*DD];
__device__ __align__(256) __nv_bfloat16 g_w2h[LL*FF*DD], g_w2l[LL*FF*DD];
__device__ __align__(256) __nv_bfloat16 g_o2h[LL*DD*FF], g_o2l[LL*DD*FF];
__device__ __align__(256) __nv_bfloat16 g_eh [VV*DD],    g_el [VV*DD];

// ======================= split helpers (hi = trunc bf16, lo = rn bf16 of remainder) ==========
__device__ __forceinline__ void split4(float4 v, uint2& hi, uint2& lo) {
    uint32_t h01 = __byte_perm(__float_as_uint(v.x), __float_as_uint(v.y), 0x7632);
    uint32_t h23 = __byte_perm(__float_as_uint(v.z), __float_as_uint(v.w), 0x7632);
    float lx = v.x - __uint_as_float(__float_as_uint(v.x) & 0xffff0000u);
    float ly = v.y - __uint_as_float(__float_as_uint(v.y) & 0xffff0000u);
    float lz = v.z - __uint_as_float(__float_as_uint(v.z) & 0xffff0000u);
    float lw = v.w - __uint_as_float(__float_as_uint(v.w) & 0xffff0000u);
    __nv_bfloat162 p01 = __floats2bfloat162_rn(lx, ly);
    __nv_bfloat162 p23 = __floats2bfloat162_rn(lz, lw);
    hi = make_uint2(h01, h23);
    lo = make_uint2(*reinterpret_cast<uint32_t*>(&p01), *reinterpret_cast<uint32_t*>(&p23));
}

__device__ __forceinline__ void split2(float2 v, uint32_t& h, uint32_t& l) {
    h = __byte_perm(__float_as_uint(v.x), __float_as_uint(v.y), 0x7632);
    float lx = v.x - __uint_as_float(__float_as_uint(v.x) & 0xffff0000u);
    float ly = v.y - __uint_as_float(__float_as_uint(v.y) & 0xffff0000u);
    __nv_bfloat162 p = __floats2bfloat162_rn(lx, ly);
    l = *reinterpret_cast<uint32_t*>(&p);
}

__global__ void split_kernel(const float* __restrict__ src, __nv_bfloat16* __restrict__ hi,
                             __nv_bfloat16* __restrict__ lo) {
    size_t i = (size_t)blockIdx.x * blockDim.x + threadIdx.x;
    float4 v = ((const float4*)src)[i];
    uint2 h, l;
    split4(v, h, l);
    ((uint2*)hi)[i] = h;
    ((uint2*)lo)[i] = l;
}

// ======================= aux kernels =======================
__device__ __forceinline__ float block_reduce_sum_256(float val) {
    #pragma unroll
    for (int o = 16; o > 0; o >>= 1) val += __shfl_xor_sync(0xffffffffu, val, o);
    __shared__ float sh[8];
    __shared__ float s_tot;
    int w = threadIdx.x >> 5;
    if ((threadIdx.x & 31) == 0) sh[w] = val;
    __syncthreads();
    if (threadIdx.x < 8) {
        float v2 = sh[threadIdx.x];
        #pragma unroll
        for (int o = 4; o > 0; o >>= 1) v2 += __shfl_xor_sync(0xffu, v2, o);
        if (threadIdx.x == 0) s_tot = v2;
    }
    __syncthreads();
    return s_tot;
}
__device__ __forceinline__ float sigmoidf_(float x) { return 1.0f / (1.0f + expf(-x)); }

// embedding gather + RMSNorm -> f32 h (residual stream)
__global__ void embed_rms_kernel(const int* __restrict__ x, const float* __restrict__ embed,
                                 const float* __restrict__ w, float* __restrict__ out) {
    int row = blockIdx.x;
    int tok = x[row];
    int t = threadIdx.x;
    float4 v = ((const float4*)(embed + (size_t)tok * DD))[t];
    float ss = v.x*v.x + v.y*v.y + v.z*v.z + v.w*v.w;
    float tot = block_reduce_sum_256(ss);
    float s = rsqrtf(tot / (float)DD + 1e-6f);
    float4 wv = ((const float4*)w)[t];
    float4 o = make_float4(v.x*s*wv.x, v.y*s*wv.y, v.z*s*wv.z, v.w*s*wv.w);
    ((float4*)(out + (size_t)row * DD))[t] = o;
}

// RMSNorm (optional elementwise gate) -> bf16 hi/lo planes (feeds GEMM A)
__global__ void rms_kernel(const float* __restrict__ x, const float* __restrict__ gate,
                           const float* __restrict__ w,
                           __nv_bfloat16* __restrict__ oh, __nv_bfloat16* __restrict__ ol) {
    int row = blockIdx.x;
    int t = threadIdx.x;
    float4 v = ((const float4*)(x + (size_t)row * DD))[t];
    if (gate != nullptr) {
        float4 g = ((const float4*)(gate + (size_t)row * DD))[t];
        v.x *= g.x; v.y *= g.y; v.z *= g.z; v.w *= g.w;
    }
    float ss = v.x*v.x + v.y*v.y + v.z*v.z + v.w*v.w;
    float tot = block_reduce_sum_256(ss);
    float s = rsqrtf(tot / (float)DD + 1e-6f);
    float4 wv = ((const float4*)w)[t];
    float4 o = make_float4(v.x*s*wv.x, v.y*s*wv.y, v.z*s*wv.z, v.w*s*wv.w);
    uint2 h, l;
    split4(o, h, l);
    ((uint2*)(oh + (size_t)row * DD))[t] = h;
    ((uint2*)(ol + (size_t)row * DD))[t] = l;
}

// TimeMix decay recurrence (exact clamped-cumsum replication)
__global__ void timemix_kernel(const float* __restrict__ k, const float* __restrict__ v,
                               const float* __restrict__ decay, float* __restrict__ state) {
    int c = blockIdx.x * blockDim.x + threadIdx.x;   // [0, BB*DD)
    int b = c / DD;
    int e = c - b * DD;
    float dec = sigmoidf_(decay[e]);
    float ln  = logf(fmaxf(dec, 1e-7f));
    size_t base = (size_t)b * TT * DD + e;
    float cum = 0.0f;
    #pragma unroll 4
    for (int t = 0; t < TT; ++t) {
        float kv = k[base + (size_t)t * DD] * v[base + (size_t)t * DD];
        float sc = expf((float)t * ln);
        cum += kv / fmaxf(sc, 1e-10f);
        state[base + (size_t)t * DD] = cum * sc;
    }
}

// ======================= common GEMM macros =======================
#define SWZ(x) ((x) ^ (((x) >> 3) & 0x70))

#define LDSM4(r, addr) \
    asm volatile("ldmatrix.sync.aligned.m8n8.x4.shared.b16 {%0,%1,%2,%3}, [%4];" \
        : "=r"((r)[0]), "=r"((r)[1]), "=r"((r)[2]), "=r"((r)[3]) : "r"(addr))

#define MMA16816(d, a, b0, b1) \
    asm volatile("mma.sync.aligned.m16n8k16.row.col.f32.bf16.bf16.f32 " \
        "{%0,%1,%2,%3}, {%4,%5,%6,%7}, {%8,%9}, {%0,%1,%2,%3};" \
        : "+f"((d)[0]), "+f"((d)[1]), "+f"((d)[2]), "+f"((d)[3]) \
        : "r"((a)[0]), "r"((a)[1]), "r"((a)[2]), "r"((a)[3]), "r"(b0), "r"(b1))

#define CP_ASYNC16(dst, src) \
    asm volatile("{ .reg .u64 g; cvta.to.global.u64 g, %1; cp.async.cg.shared.global [%0], [g], 16; }" \
        :: "r"(dst), "l"(src) : "memory")
#define CP_COMMIT() asm volatile("cp.async.commit_group;" ::: "memory")
#define CP_WAIT2()  asm volatile("cp.async.wait_group 2;" ::: "memory")
#define CP_WAIT1()  asm volatile("cp.async.wait_group 1;" ::: "memory")
#define CP_WAIT0()  asm volatile("cp.async.wait_group 0;" ::: "memory")

__device__ __forceinline__ uint32_t smem_u32(const void* p) {
    uint32_t a;
    asm("{ .reg .u64 t; cvta.to.shared.u64 t, %1; cvt.u32.u64 %0, t; }" : "=r"(a) : "l"(p));
    return a;
}

// ======================= GEMM: CTA 128x128, 256 thr, 8 warps (2M x 4N), warp 64x32 ======
// Fragment double-buffered over kk; single-barrier 3-stage cp.async pipeline.
// Verified fragment layout: LDSM4 -> {n0k0, n0k1, n1k0, n1k1};
// m16n8k16 B pair for n-sub s = (r[2s], r[2s+1]).
// epi: 0 = store f32, 1 = sigmoid, 2 = residual add,
//      3 = fused gate: out = silu(G) * acc -> split bf16 to OH/OL.
#define PLANE 16384
#define STAGEB 65536   // 4 planes x 128 rows x 128B
#define NST 3

__global__ void __launch_bounds__(256)
gemm_hmma(const __nv_bfloat16* __restrict__ Ah, const __nv_bfloat16* __restrict__ Al,
          const __nv_bfloat16* __restrict__ Bh, const __nv_bfloat16* __restrict__ Bl,
          float* __restrict__ C, const float* __restrict__ G,
          __nv_bfloat16* __restrict__ OH, __nv_bfloat16* __restrict__ OL,
          int N, int K, int epi) {
    extern __shared__ __align__(1024) char smem[];
    const uint32_t sb = smem_u32(smem);
    const int tid  = threadIdx.x;
    const int lane = tid & 31, wid = tid >> 5;
    const int wm = wid & 1;          // m offset wm*64
    const int wn = wid >> 1;         // 0..3 -> n offset wn*32
    const int bm = blockIdx.y * 128, bn = blockIdx.x * 128;

    // cp.async: 2 threads per 128B row per plane; 4x16B each
    const int lr = tid >> 1;
    const int lq = (tid & 1) * 4;
    const __nv_bfloat16* psrc[4] = {
        Ah + (size_t)(bm + lr) * K + lq * 8,
        Al + (size_t)(bm + lr) * K + lq * 8,
        Bh + (size_t)(bn + lr) * K + lq * 8,
        Bl + (size_t)(bn + lr) * K + lq * 8
    };
    uint32_t dsw[4];
    #pragma unroll
    for (int j = 0; j < 4; ++j) dsw[j] = SWZ((uint32_t)(lr * 128 + (lq + j) * 16));

    const uint32_t aoff0 = (uint32_t)(wm * 64 + (lane & 15)) * 128 + (lane >> 4) * 16;
    const uint32_t boff0 = (uint32_t)(wn * 32 + ((lane >> 4) & 1) * 8 + (lane & 7)) * 128
                         + ((lane >> 3) & 1) * 16;

    float acc[4][4][4];
    #pragma unroll
    for (int mt = 0; mt < 4; ++mt)
        #pragma unroll
        for (int nt = 0; nt < 4; ++nt)
            #pragma unroll
            for (int q = 0; q < 4; ++q) acc[mt][nt][q] = 0.0f;

    const int nch = K >> 6;

    // prologue: chunks 0,1,2 into stages 0,1,2
    #pragma unroll
    for (int s = 0; s < 3; ++s) {
        const uint32_t st = sb + s * STAGEB;
        const int koff = s * 64;
        #pragma unroll
        for (int p = 0; p < 4; ++p)
            #pragma unroll
            for (int j = 0; j < 4; ++j)
                CP_ASYNC16(st + p * PLANE + dsw[j], psrc[p] + koff + j * 8);
        CP_COMMIT();
    }
    CP_WAIT2();
    __syncthreads();

    // double-buffered fragments
    uint32_t ah[2][4][4], al[2][4][4], bhf[2][2][4], blf[2][2][4];

    int buf = 0;
    for (int ch = 0; ch < nch; ++ch) {
        const uint32_t st = sb + buf * STAGEB;
        // load kk=0 frags into fb 0
        #pragma unroll
        for (int mt = 0; mt < 4; ++mt) {
            uint32_t o = SWZ(aoff0 + mt * 2048);
            LDSM4(ah[0][mt], st + o);
            LDSM4(al[0][mt], st + PLANE + o);
        }
        #pragma unroll
        for (int np = 0; np < 2; ++np) {
            uint32_t o = SWZ(boff0 + np * 2048);
            LDSM4(bhf[0][np], st + 2 * PLANE + o);
            LDSM4(blf[0][np], st + 3 * PLANE + o);
        }
        #pragma unroll
        for (int kk = 0; kk < 4; ++kk) {
            const int fb = kk & 1;
            if (kk < 3) {
                const int nf = fb ^ 1;
                #pragma unroll
                for (int mt = 0; mt < 4; ++mt) {
                    uint32_t o = SWZ(aoff0 + mt * 2048 + (kk + 1) * 32);
                    LDSM4(ah[nf][mt], st + o);
                    LDSM4(al[nf][mt], st + PLANE + o);
                }
                #pragma unroll
                for (int np = 0; np < 2; ++np) {
                    uint32_t o = SWZ(boff0 + np * 2048 + (kk + 1) * 32);
                    LDSM4(bhf[nf][np], st + 2 * PLANE + o);
                    LDSM4(blf[nf][np], st + 3 * PLANE + o);
                }
            }
            // hh
            #pragma unroll
            for (int mt = 0; mt < 4; ++mt)
                #pragma unroll
                for (int nt = 0; nt < 4; ++nt)
                    MMA16816(acc[mt][nt], ah[fb][mt],
                             bhf[fb][nt >> 1][(nt & 1) * 2], bhf[fb][nt >> 1][(nt & 1) * 2 + 1]);
            // hl
            #pragma unroll
            for (int mt = 0; mt < 4; ++mt)
                #pragma unroll
                for (int nt = 0; nt < 4; ++nt)
                    MMA16816(acc[mt][nt], ah[fb][mt],
                             blf[fb][nt >> 1][(nt & 1) * 2], blf[fb][nt >> 1][(nt & 1) * 2 + 1]);
            // lh
            #pragma unroll
            for (int mt = 0; mt < 4; ++mt)
                #pragma unroll
                for (int nt = 0; nt < 4; ++nt)
                    MMA16816(acc[mt][nt], al[fb][mt],
                             bhf[fb][nt >> 1][(nt & 1) * 2], bhf[fb][nt >> 1][(nt & 1) * 2 + 1]);
        }
        // wait for chunk ch+1 (already issued)
        if (ch + 2 < nch)      CP_WAIT1();
        else if (ch + 1 < nch) CP_WAIT0();
        __syncthreads();   // (a) all warps done with buf; (b) chunk ch+1 visible
        if (ch + 3 < nch) {
            const int koff = (ch + 3) * 64;
            #pragma unroll
            for (int p = 0; p < 4; ++p)
                #pragma unroll
                for (int j = 0; j < 4; ++j)
                    CP_ASYNC16(st + p * PLANE + dsw[j], psrc[p] + koff + j * 8);
            CP_COMMIT();
        }
        ++buf; if (buf == NST) buf = 0;
    }

    // epilogue
    const int g  = lane >> 2;
    const int tc = lane & 3;
    #pragma unroll
    for (int mt = 0; mt < 4; ++mt) {
        #pragma unroll
        for (int nt = 0; nt < 4; ++nt) {
            const int r0 = bm + wm * 64 + mt * 16 + g;
            const int c  = bn + wn * 32 + nt * 8 + tc * 2;
            float2 v0 = make_float2(acc[mt][nt][0], acc[mt][nt][1]);
            float2 v1 = make_float2(acc[mt][nt][2], acc[mt][nt][3]);
            if (epi == 3) {
                const float2 q0 = *(const float2*)(G + (size_t)r0 * N + c);
                const float2 q1 = *(const float2*)(G + (size_t)(r0 + 8) * N + c);
                v0.x *= q0.x * sigmoidf_(q0.x); v0.y *= q0.y * sigmoidf_(q0.y);
                v1.x *= q1.x * sigmoidf_(q1.x); v1.y *= q1.y * sigmoidf_(q1.y);
                uint32_t h0, l0, h1, l1;
                split2(v0, h0, l0);
                split2(v1, h1, l1);
                *(uint32_t*)(OH + (size_t)r0 * N + c)       = h0;
                *(uint32_t*)(OL + (size_t)r0 * N + c)       = l0;
                *(uint32_t*)(OH + (size_t)(r0 + 8) * N + c) = h1;
                *(uint32_t*)(OL + (size_t)(r0 + 8) * N + c) = l1;
            } else {
                float* p0 = C + (size_t)r0 * N + c;
                float* p1 = C + (size_t)(r0 + 8) * N + c;
                if (epi == 1) {
                    v0.x = sigmoidf_(v0.x); v0.y = sigmoidf_(v0.y);
                    v1.x = sigmoidf_(v1.x); v1.y = sigmoidf_(v1.y);
                } else if (epi == 2) {
                    float2 c0 = *(const float2*)p0;
                    float2 c1 = *(const float2*)p1;
                    v0.x += c0.x; v0.y += c0.y;
                    v1.x += c1.x; v1.y += c1.y;
                }
                *(float2*)p0 = v0;
                *(float2*)p1 = v1;
            }
        }
    }
}

// ======================= launch =======================
extern "C" void kernel_launch(void* const* d_in, const int* in_sizes, int n_in,
                              void* d_out, int out_size) {
    const int*   x      = (const int*)  d_in[0];
    const float* embed  = (const float*)d_in[1];
    const float* ln_in  = (const float*)d_in[2];
    const float* ln_out = (const float*)d_in[3];
    const float* ln1    = (const float*)d_in[4];
    const float* Wr     = (const float*)d_in[5];
    const float* Wk     = (const float*)d_in[6];
    const float* Wv     = (const float*)d_in[7];
    const float* Wo     = (const float*)d_in[8];
    const float* decay  = (const float*)d_in[9];
    const float* lnx    = (const float*)d_in[10];
    const float* ln2    = (const float*)d_in[11];
    const float* W1     = (const float*)d_in[12];
    const float* W2     = (const float*)d_in[13];
    const float* Wo2    = (const float*)d_in[14];
    float* out = (float*)d_out;

    float *h, *r, *k, *v, *st, *g1;
    __nv_bfloat16 *xnh, *xnl, *gh, *gl;
    __nv_bfloat16 *wrh, *wrl, *wkh, *wkl, *wvh, *wvl, *woh, *wol;
    __nv_bfloat16 *w1h, *w1l, *w2h, *w2l, *o2h, *o2l, *eh, *el;
    cudaGetSymbolAddress((void**)&h,  g_h);   cudaGetSymbolAddress((void**)&r,  g_r);
    cudaGetSymbolAddress((void**)&k,  g_k);   cudaGetSymbolAddress((void**)&v,  g_v);
    cudaGetSymbolAddress((void**)&st, g_st);  cudaGetSymbolAddress((void**)&g1, g_g1);
    cudaGetSymbolAddress((void**)&xnh, g_xnh); cudaGetSymbolAddress((void**)&xnl, g_xnl);
    cudaGetSymbolAddress((void**)&gh,  g_gh);  cudaGetSymbolAddress((void**)&gl,  g_gl);
    cudaGetSymbolAddress((void**)&wrh, g_wrh); cudaGetSymbolAddress((void**)&wrl, g_wrl);
    cudaGetSymbolAddress((void**)&wkh, g_wkh); cudaGetSymbolAddress((void**)&wkl, g_wkl);
    cudaGetSymbolAddress((void**)&wvh, g_wvh); cudaGetSymbolAddress((void**)&wvl, g_wvl);
    cudaGetSymbolAddress((void**)&woh, g_woh); cudaGetSymbolAddress((void**)&wol, g_wol);
    cudaGetSymbolAddress((void**)&w1h, g_w1h); cudaGetSymbolAddress((void**)&w1l, g_w1l);
    cudaGetSymbolAddress((void**)&w2h, g_w2h); cudaGetSymbolAddress((void**)&w2l, g_w2l);
    cudaGetSymbolAddress((void**)&o2h, g_o2h); cudaGetSymbolAddress((void**)&o2l, g_o2l);
    cudaGetSymbolAddress((void**)&eh,  g_eh);  cudaGetSymbolAddress((void**)&el,  g_el);

    const int SMEM = NST * STAGEB;   // 196608
    cudaFuncSetAttribute(gemm_hmma, cudaFuncAttributeMaxDynamicSharedMemorySize, SMEM);

    const dim3 blk(256);
    const dim3 gblk(256);
    const dim3 gD(DD / 128, MM / 128);     // 8 x 16
    const dim3 gF(FF / 128, MM / 128);     // 32 x 16
    const dim3 gH(VV / 128, MM / 128);     // 250 x 16

    // ---- launch order: my index 3 = D-GEMM (profiled) ----
    split_kernel<<<(LL*DD*DD)/1024, blk>>>(Wr,  wrh, wrl);                  // #0
    embed_rms_kernel<<<MM, blk>>>(x, embed, ln_in, h);                      // #1
    rms_kernel<<<MM, blk>>>(h, nullptr, ln1, xnh, xnl);                     // #2
    gemm_hmma<<<gD, gblk, SMEM>>>(xnh, xnl, wrh, wrl, r, nullptr, nullptr, nullptr, DD, DD, 1); // #3

    // remaining splits
    split_kernel<<<(LL*DD*DD)/1024, blk>>>(Wk,  wkh, wkl);
    split_kernel<<<(LL*DD*DD)/1024, blk>>>(Wv,  wvh, wvl);
    split_kernel<<<(LL*DD*DD)/1024, blk>>>(Wo,  woh, wol);
    split_kernel<<<(LL*FF*DD)/1024, blk>>>(W1,  w1h, w1l);
    split_kernel<<<(LL*FF*DD)/1024, blk>>>(W2,  w2h, w2l);
    split_kernel<<<(LL*DD*FF)/1024, blk>>>(Wo2, o2h, o2l);
    split_kernel<<<(VV*DD)/1024,    blk>>>(embed, eh, el);

    for (int l = 0; l < LL; ++l) {
        const size_t oDD = (size_t)l * DD * DD;
        const size_t oFD = (size_t)l * FF * DD;

        // --- TimeMix ---
        if (l > 0)
            rms_kernel<<<MM, blk>>>(h, nullptr, ln1 + l * DD, xnh, xnl);
        if (l > 0)
            gemm_hmma<<<gD, gblk, SMEM>>>(xnh, xnl, wrh + oDD, wrl + oDD, r,
                                          nullptr, nullptr, nullptr, DD, DD, 1);
        gemm_hmma<<<gD, gblk, SMEM>>>(xnh, xnl, wkh + oDD, wkl + oDD, k,
                                      nullptr, nullptr, nullptr, DD, DD, 0);
        gemm_hmma<<<gD, gblk, SMEM>>>(xnh, xnl, wvh + oDD, wvl + oDD, v,
                                      nullptr, nullptr, nullptr, DD, DD, 0);
        timemix_kernel<<<(BB * DD) / 256, blk>>>(k, v, decay + l * DD, st);
        rms_kernel<<<MM, blk>>>(st, r, lnx + l * DD, xnh, xnl);
        gemm_hmma<<<gD, gblk, SMEM>>>(xnh, xnl, woh + oDD, wol + oDD, h,
                                      nullptr, nullptr, nullptr, DD, DD, 2);

        // --- ChannelMix (gate fused into W2 epilogue) ---
        rms_kernel<<<MM, blk>>>(h, nullptr, ln2 + l * DD, xnh, xnl);
        gemm_hmma<<<gF, gblk, SMEM>>>(xnh, xnl, w1h + oFD, w1l + oFD, g1,
                                      nullptr, nullptr, nullptr, FF, DD, 0);
        gemm_hmma<<<gF, gblk, SMEM>>>(xnh, xnl, w2h + oFD, w2l + oFD, nullptr,
                                      g1, gh, gl, FF, DD, 3);
        gemm_hmma<<<gD, gblk, SMEM>>>(gh, gl, o2h + oFD, o2l + oFD, h,
                                      nullptr, nullptr, nullptr, DD, FF, 2);
    }

    // --- tied head ---
    rms_kernel<<<MM, blk>>>(h, nullptr, ln_out, xnh, xnl);
    gemm_hmma<<<gH, gblk, SMEM>>>(xnh, xnl, eh, el, out,
                                  nullptr, nullptr, nullptr, VV, DD, 0);
}

// round 14
// speedup vs baseline: 1.2444x; 1.2444x over previous
#include <cuda_runtime.h>
#include <cuda_bf16.h>
#include <stdint.h>
#include <math.h>

#define BB 8
#define TT 256
#define DD 1024
#define LL 12
#define FF 4096
#define VV 32000
#define MM (BB*TT)   // 2048 rows

// ======================= scratch (static device globals; no runtime alloc) =======================
__device__ __align__(256) float g_h [MM*DD];
__device__ __align__(256) float g_r [MM*DD];
__device__ __align__(256) float g_k [MM*DD];
__device__ __align__(256) float g_v [MM*DD];
__device__ __align__(256) float g_st[MM*DD];
__device__ __align__(256) float g_g1[MM*FF];

__device__ __align__(256) __nv_bfloat16 g_xnh[MM*DD], g_xnl[MM*DD];
__device__ __align__(256) __nv_bfloat16 g_gh [MM*FF], g_gl [MM*FF];

__device__ __align__(256) __nv_bfloat16 g_wrh[LL*DD*DD], g_wrl[LL*DD*DD];
__device__ __align__(256) __nv_bfloat16 g_wkh[LL*DD*DD], g_wkl[LL*DD*DD];
__device__ __align__(256) __nv_bfloat16 g_wvh[LL*DD*DD], g_wvl[LL*DD*DD];
__device__ __align__(256) __nv_bfloat16 g_woh[LL*DD*DD], g_wol[LL*DD*DD];
__device__ __align__(256) __nv_bfloat16 g_w1h[LL*FF*DD], g_w1l[LL*FF*DD];
__device__ __align__(256) __nv_bfloat16 g_w2h[LL*FF*DD], g_w2l[LL*FF*DD];
__device__ __align__(256) __nv_bfloat16 g_o2h[LL*DD*FF], g_o2l[LL*DD*FF];
__device__ __align__(256) __nv_bfloat16 g_eh [VV*DD],    g_el [VV*DD];

// ======================= split helpers (hi = trunc bf16, lo = rn bf16 of remainder) ==========
__device__ __forceinline__ void split4(float4 v, uint2& hi, uint2& lo) {
    uint32_t h01 = __byte_perm(__float_as_uint(v.x), __float_as_uint(v.y), 0x7632);
    uint32_t h23 = __byte_perm(__float_as_uint(v.z), __float_as_uint(v.w), 0x7632);
    float lx = v.x - __uint_as_float(__float_as_uint(v.x) & 0xffff0000u);
    float ly = v.y - __uint_as_float(__float_as_uint(v.y) & 0xffff0000u);
    float lz = v.z - __uint_as_float(__float_as_uint(v.z) & 0xffff0000u);
    float lw = v.w - __uint_as_float(__float_as_uint(v.w) & 0xffff0000u);
    __nv_bfloat162 p01 = __floats2bfloat162_rn(lx, ly);
    __nv_bfloat162 p23 = __floats2bfloat162_rn(lz, lw);
    hi = make_uint2(h01, h23);
    lo = make_uint2(*reinterpret_cast<uint32_t*>(&p01), *reinterpret_cast<uint32_t*>(&p23));
}

__device__ __forceinline__ void split2(float2 v, uint32_t& h, uint32_t& l) {
    h = __byte_perm(__float_as_uint(v.x), __float_as_uint(v.y), 0x7632);
    float lx = v.x - __uint_as_float(__float_as_uint(v.x) & 0xffff0000u);
    float ly = v.y - __uint_as_float(__float_as_uint(v.y) & 0xffff0000u);
    __nv_bfloat162 p = __floats2bfloat162_rn(lx, ly);
    l = *reinterpret_cast<uint32_t*>(&p);
}

__global__ void split_kernel(const float* __restrict__ src, __nv_bfloat16* __restrict__ hi,
                             __nv_bfloat16* __restrict__ lo) {
    size_t i = (size_t)blockIdx.x * blockDim.x + threadIdx.x;
    float4 v = ((const float4*)src)[i];
    uint2 h, l;
    split4(v, h, l);
    ((uint2*)hi)[i] = h;
    ((uint2*)lo)[i] = l;
}

// ======================= aux kernels =======================
__device__ __forceinline__ float block_reduce_sum_256(float val) {
    #pragma unroll
    for (int o = 16; o > 0; o >>= 1) val += __shfl_xor_sync(0xffffffffu, val, o);
    __shared__ float sh[8];
    __shared__ float s_tot;
    int w = threadIdx.x >> 5;
    if ((threadIdx.x & 31) == 0) sh[w] = val;
    __syncthreads();
    if (threadIdx.x < 8) {
        float v2 = sh[threadIdx.x];
        #pragma unroll
        for (int o = 4; o > 0; o >>= 1) v2 += __shfl_xor_sync(0xffu, v2, o);
        if (threadIdx.x == 0) s_tot = v2;
    }
    __syncthreads();
    return s_tot;
}
__device__ __forceinline__ float sigmoidf_(float x) { return 1.0f / (1.0f + expf(-x)); }

// embedding gather + RMSNorm -> f32 h (residual stream)
__global__ void embed_rms_kernel(const int* __restrict__ x, const float* __restrict__ embed,
                                 const float* __restrict__ w, float* __restrict__ out) {
    int row = blockIdx.x;
    int tok = x[row];
    int t = threadIdx.x;
    float4 v = ((const float4*)(embed + (size_t)tok * DD))[t];
    float ss = v.x*v.x + v.y*v.y + v.z*v.z + v.w*v.w;
    float tot = block_reduce_sum_256(ss);
    float s = rsqrtf(tot / (float)DD + 1e-6f);
    float4 wv = ((const float4*)w)[t];
    float4 o = make_float4(v.x*s*wv.x, v.y*s*wv.y, v.z*s*wv.z, v.w*s*wv.w);
    ((float4*)(out + (size_t)row * DD))[t] = o;
}

// RMSNorm (optional elementwise gate) -> bf16 hi/lo planes (feeds GEMM A)
__global__ void rms_kernel(const float* __restrict__ x, const float* __restrict__ gate,
                           const float* __restrict__ w,
                           __nv_bfloat16* __restrict__ oh, __nv_bfloat16* __restrict__ ol) {
    int row = blockIdx.x;
    int t = threadIdx.x;
    float4 v = ((const float4*)(x + (size_t)row * DD))[t];
    if (gate != nullptr) {
        float4 g = ((const float4*)(gate + (size_t)row * DD))[t];
        v.x *= g.x; v.y *= g.y; v.z *= g.z; v.w *= g.w;
    }
    float ss = v.x*v.x + v.y*v.y + v.z*v.z + v.w*v.w;
    float tot = block_reduce_sum_256(ss);
    float s = rsqrtf(tot / (float)DD + 1e-6f);
    float4 wv = ((const float4*)w)[t];
    float4 o = make_float4(v.x*s*wv.x, v.y*s*wv.y, v.z*s*wv.z, v.w*s*wv.w);
    uint2 h, l;
    split4(o, h, l);
    ((uint2*)(oh + (size_t)row * DD))[t] = h;
    ((uint2*)(ol + (size_t)row * DD))[t] = l;
}

// TimeMix decay recurrence (exact clamped-cumsum replication)
__global__ void timemix_kernel(const float* __restrict__ k, const float* __restrict__ v,
                               const float* __restrict__ decay, float* __restrict__ state) {
    int c = blockIdx.x * blockDim.x + threadIdx.x;   // [0, BB*DD)
    int b = c / DD;
    int e = c - b * DD;
    float dec = sigmoidf_(decay[e]);
    float ln  = logf(fmaxf(dec, 1e-7f));
    size_t base = (size_t)b * TT * DD + e;
    float cum = 0.0f;
    #pragma unroll 4
    for (int t = 0; t < TT; ++t) {
        float kv = k[base + (size_t)t * DD] * v[base + (size_t)t * DD];
        float sc = expf((float)t * ln);
        cum += kv / fmaxf(sc, 1e-10f);
        state[base + (size_t)t * DD] = cum * sc;
    }
}

// ======================= common GEMM macros =======================
#define SWZ(x) ((x) ^ (((x) >> 3) & 0x70))

#define LDSM4(r, addr) \
    asm volatile("ldmatrix.sync.aligned.m8n8.x4.shared.b16 {%0,%1,%2,%3}, [%4];" \
        : "=r"((r)[0]), "=r"((r)[1]), "=r"((r)[2]), "=r"((r)[3]) : "r"(addr))

#define MMA16816(d, a, b0, b1) \
    asm volatile("mma.sync.aligned.m16n8k16.row.col.f32.bf16.bf16.f32 " \
        "{%0,%1,%2,%3}, {%4,%5,%6,%7}, {%8,%9}, {%0,%1,%2,%3};" \
        : "+f"((d)[0]), "+f"((d)[1]), "+f"((d)[2]), "+f"((d)[3]) \
        : "r"((a)[0]), "r"((a)[1]), "r"((a)[2]), "r"((a)[3]), "r"(b0), "r"(b1))

#define CP_ASYNC16(dst, src) \
    asm volatile("{ .reg .u64 g; cvta.to.global.u64 g, %1; cp.async.cg.shared.global [%0], [g], 16; }" \
        :: "r"(dst), "l"(src) : "memory")
#define CP_COMMIT() asm volatile("cp.async.commit_group;" ::: "memory")
#define CP_WAIT2()  asm volatile("cp.async.wait_group 2;" ::: "memory")
#define CP_WAIT1()  asm volatile("cp.async.wait_group 1;" ::: "memory")
#define CP_WAIT0()  asm volatile("cp.async.wait_group 0;" ::: "memory")

__device__ __forceinline__ uint32_t smem_u32(const void* p) {
    uint32_t a;
    asm("{ .reg .u64 t; cvta.to.shared.u64 t, %1; cvt.u32.u64 %0, t; }" : "=r"(a) : "l"(p));
    return a;
}

// ======================= GEMM: CTA 128x128, 1024 thr, 32 warps (4M x 8N), warp 32x16 ======
// Single-barrier 3-stage cp.async pipeline (R12-verified core).
// Fragment layout: LDSM4 -> {n0k0, n0k1, n1k0, n1k1}; B pair for n-sub s = (r[2s], r[2s+1]).
// epi: 0 = store f32, 1 = sigmoid, 2 = residual add,
//      3 = fused gate: out = silu(G) * acc -> split bf16 to OH/OL.
#define PLANE 16384
#define STAGE128 65536   // 4 planes x 128 rows x 128B
#define NST128 3

__global__ void __launch_bounds__(1024)
gemm_hmma(const __nv_bfloat16* __restrict__ Ah, const __nv_bfloat16* __restrict__ Al,
          const __nv_bfloat16* __restrict__ Bh, const __nv_bfloat16* __restrict__ Bl,
          float* __restrict__ C, const float* __restrict__ G,
          __nv_bfloat16* __restrict__ OH, __nv_bfloat16* __restrict__ OL,
          int N, int K, int epi) {
    extern __shared__ __align__(1024) char smem[];
    const uint32_t sb = smem_u32(smem);
    const int tid  = threadIdx.x;
    const int lane = tid & 31, wid = tid >> 5;
    const int wm = wid & 3;          // m offset wm*32
    const int wn = wid >> 2;         // 0..7 -> n offset wn*16
    const int bm = blockIdx.y * 128, bn = blockIdx.x * 128;

    // cp.async: 8 threads per 128B row per plane; 1x16B each
    const int lr = tid >> 3;
    const int lq = tid & 7;
    const __nv_bfloat16* psrc[4] = {
        Ah + (size_t)(bm + lr) * K + lq * 8,
        Al + (size_t)(bm + lr) * K + lq * 8,
        Bh + (size_t)(bn + lr) * K + lq * 8,
        Bl + (size_t)(bn + lr) * K + lq * 8
    };
    const uint32_t dsw = SWZ((uint32_t)(lr * 128 + lq * 16));

    const uint32_t aoff0 = (uint32_t)(wm * 32 + (lane & 15)) * 128 + (lane >> 4) * 16;
    const uint32_t boff0 = (uint32_t)(wn * 16 + ((lane >> 4) & 1) * 8 + (lane & 7)) * 128
                         + ((lane >> 3) & 1) * 16;

    float acc[2][2][4];
    #pragma unroll
    for (int mt = 0; mt < 2; ++mt)
        #pragma unroll
        for (int nt = 0; nt < 2; ++nt)
            #pragma unroll
            for (int q = 0; q < 4; ++q) acc[mt][nt][q] = 0.0f;

    const int nch = K >> 6;

    // prologue: chunks 0,1,2 into stages 0,1,2
    #pragma unroll
    for (int s = 0; s < 3; ++s) {
        const uint32_t st = sb + s * STAGE128;
        const int koff = s * 64;
        #pragma unroll
        for (int p = 0; p < 4; ++p)
            CP_ASYNC16(st + p * PLANE + dsw, psrc[p] + koff);
        CP_COMMIT();
    }
    CP_WAIT2();        // chunk 0 arrived
    __syncthreads();

    int buf = 0;
    for (int ch = 0; ch < nch; ++ch) {
        const uint32_t st = sb + buf * STAGE128;
        #pragma unroll
        for (int kk = 0; kk < 4; ++kk) {
            uint32_t ah[2][4], al[2][4], bh[4], bl[4];
            #pragma unroll
            for (int mt = 0; mt < 2; ++mt) {
                uint32_t o = SWZ(aoff0 + mt * 2048 + kk * 32);
                LDSM4(ah[mt], st + o);
                LDSM4(al[mt], st + PLANE + o);
            }
            {
                uint32_t o = SWZ(boff0 + kk * 32);
                LDSM4(bh, st + 2 * PLANE + o);
                LDSM4(bl, st + 3 * PLANE + o);
            }
            #pragma unroll
            for (int mt = 0; mt < 2; ++mt)
                #pragma unroll
                for (int nt = 0; nt < 2; ++nt)
                    MMA16816(acc[mt][nt], ah[mt], bh[nt * 2], bh[nt * 2 + 1]);
            #pragma unroll
            for (int mt = 0; mt < 2; ++mt)
                #pragma unroll
                for (int nt = 0; nt < 2; ++nt)
                    MMA16816(acc[mt][nt], ah[mt], bl[nt * 2], bl[nt * 2 + 1]);
            #pragma unroll
            for (int mt = 0; mt < 2; ++mt)
                #pragma unroll
                for (int nt = 0; nt < 2; ++nt)
                    MMA16816(acc[mt][nt], al[mt], bh[nt * 2], bh[nt * 2 + 1]);
        }
        // wait for chunk ch+1 (issued >= 1 iteration ago)
        if (ch + 2 < nch)      CP_WAIT1();
        else if (ch + 1 < nch) CP_WAIT0();
        __syncthreads();   // (a) all warps done with buf; (b) chunk ch+1 visible
        if (ch + 3 < nch) {
            const int koff = (ch + 3) * 64;
            #pragma unroll
            for (int p = 0; p < 4; ++p)
                CP_ASYNC16(st + p * PLANE + dsw, psrc[p] + koff);
            CP_COMMIT();
        }
        ++buf; if (buf == NST128) buf = 0;
    }

    // epilogue
    const int g  = lane >> 2;
    const int tc = lane & 3;
    #pragma unroll
    for (int mt = 0; mt < 2; ++mt) {
        #pragma unroll
        for (int nt = 0; nt < 2; ++nt) {
            const int r0 = bm + wm * 32 + mt * 16 + g;
            const int c  = bn + wn * 16 + nt * 8 + tc * 2;
            float2 v0 = make_float2(acc[mt][nt][0], acc[mt][nt][1]);
            float2 v1 = make_float2(acc[mt][nt][2], acc[mt][nt][3]);
            if (epi == 3) {
                const float2 q0 = *(const float2*)(G + (size_t)r0 * N + c);
                const float2 q1 = *(const float2*)(G + (size_t)(r0 + 8) * N + c);
                v0.x *= q0.x * sigmoidf_(q0.x); v0.y *= q0.y * sigmoidf_(q0.y);
                v1.x *= q1.x * sigmoidf_(q1.x); v1.y *= q1.y * sigmoidf_(q1.y);
                uint32_t h0, l0, h1, l1;
                split2(v0, h0, l0);
                split2(v1, h1, l1);
                *(uint32_t*)(OH + (size_t)r0 * N + c)       = h0;
                *(uint32_t*)(OL + (size_t)r0 * N + c)       = l0;
                *(uint32_t*)(OH + (size_t)(r0 + 8) * N + c) = h1;
                *(uint32_t*)(OL + (size_t)(r0 + 8) * N + c) = l1;
            } else {
                float* p0 = C + (size_t)r0 * N + c;
                float* p1 = C + (size_t)(r0 + 8) * N + c;
                if (epi == 1) {
                    v0.x = sigmoidf_(v0.x); v0.y = sigmoidf_(v0.y);
                    v1.x = sigmoidf_(v1.x); v1.y = sigmoidf_(v1.y);
                } else if (epi == 2) {
                    float2 c0 = *(const float2*)p0;
                    float2 c1 = *(const float2*)p1;
                    v0.x += c0.x; v0.y += c0.y;
                    v1.x += c1.x; v1.y += c1.y;
                }
                *(float2*)p0 = v0;
                *(float2*)p1 = v1;
            }
        }
    }
}

// ======================= launch =======================
extern "C" void kernel_launch(void* const* d_in, const int* in_sizes, int n_in,
                              void* d_out, int out_size) {
    const int*   x      = (const int*)  d_in[0];
    const float* embed  = (const float*)d_in[1];
    const float* ln_in  = (const float*)d_in[2];
    const float* ln_out = (const float*)d_in[3];
    const float* ln1    = (const float*)d_in[4];
    const float* Wr     = (const float*)d_in[5];
    const float* Wk     = (const float*)d_in[6];
    const float* Wv     = (const float*)d_in[7];
    const float* Wo     = (const float*)d_in[8];
    const float* decay  = (const float*)d_in[9];
    const float* lnx    = (const float*)d_in[10];
    const float* ln2    = (const float*)d_in[11];
    const float* W1     = (const float*)d_in[12];
    const float* W2     = (const float*)d_in[13];
    const float* Wo2    = (const float*)d_in[14];
    float* out = (float*)d_out;

    float *h, *r, *k, *v, *st, *g1;
    __nv_bfloat16 *xnh, *xnl, *gh, *gl;
    __nv_bfloat16 *wrh, *wrl, *wkh, *wkl, *wvh, *wvl, *woh, *wol;
    __nv_bfloat16 *w1h, *w1l, *w2h, *w2l, *o2h, *o2l, *eh, *el;
    cudaGetSymbolAddress((void**)&h,  g_h);   cudaGetSymbolAddress((void**)&r,  g_r);
    cudaGetSymbolAddress((void**)&k,  g_k);   cudaGetSymbolAddress((void**)&v,  g_v);
    cudaGetSymbolAddress((void**)&st, g_st);  cudaGetSymbolAddress((void**)&g1, g_g1);
    cudaGetSymbolAddress((void**)&xnh, g_xnh); cudaGetSymbolAddress((void**)&xnl, g_xnl);
    cudaGetSymbolAddress((void**)&gh,  g_gh);  cudaGetSymbolAddress((void**)&gl,  g_gl);
    cudaGetSymbolAddress((void**)&wrh, g_wrh); cudaGetSymbolAddress((void**)&wrl, g_wrl);
    cudaGetSymbolAddress((void**)&wkh, g_wkh); cudaGetSymbolAddress((void**)&wkl, g_wkl);
    cudaGetSymbolAddress((void**)&wvh, g_wvh); cudaGetSymbolAddress((void**)&wvl, g_wvl);
    cudaGetSymbolAddress((void**)&woh, g_woh); cudaGetSymbolAddress((void**)&wol, g_wol);
    cudaGetSymbolAddress((void**)&w1h, g_w1h); cudaGetSymbolAddress((void**)&w1l, g_w1l);
    cudaGetSymbolAddress((void**)&w2h, g_w2h); cudaGetSymbolAddress((void**)&w2l, g_w2l);
    cudaGetSymbolAddress((void**)&o2h, g_o2h); cudaGetSymbolAddress((void**)&o2l, g_o2l);
    cudaGetSymbolAddress((void**)&eh,  g_eh);  cudaGetSymbolAddress((void**)&el,  g_el);

    const int SMEM = NST128 * STAGE128;   // 196608
    cudaFuncSetAttribute(gemm_hmma, cudaFuncAttributeMaxDynamicSharedMemorySize, SMEM);

    const dim3 blk(256);
    const dim3 gblk(1024);
    const dim3 gD(DD / 128, MM / 128);     // 8 x 16
    const dim3 gF(FF / 128, MM / 128);     // 32 x 16
    const dim3 gH(VV / 128, MM / 128);     // 250 x 16

    // ---- launch order: my index 3 = D-GEMM (profiled) ----
    split_kernel<<<(LL*DD*DD)/1024, blk>>>(Wr,  wrh, wrl);                  // #0
    embed_rms_kernel<<<MM, blk>>>(x, embed, ln_in, h);                      // #1
    rms_kernel<<<MM, blk>>>(h, nullptr, ln1, xnh, xnl);                     // #2
    gemm_hmma<<<gD, gblk, SMEM>>>(xnh, xnl, wrh, wrl, r,
                                  nullptr, nullptr, nullptr, DD, DD, 1);    // #3 <-- profiled

    // remaining splits
    split_kernel<<<(LL*DD*DD)/1024, blk>>>(Wk,  wkh, wkl);
    split_kernel<<<(LL*DD*DD)/1024, blk>>>(Wv,  wvh, wvl);
    split_kernel<<<(LL*DD*DD)/1024, blk>>>(Wo,  woh, wol);
    split_kernel<<<(LL*FF*DD)/1024, blk>>>(W1,  w1h, w1l);
    split_kernel<<<(LL*FF*DD)/1024, blk>>>(W2,  w2h, w2l);
    split_kernel<<<(LL*DD*FF)/1024, blk>>>(Wo2, o2h, o2l);
    split_kernel<<<(VV*DD)/1024,    blk>>>(embed, eh, el);

    for (int l = 0; l < LL; ++l) {
        const size_t oDD = (size_t)l * DD * DD;
        const size_t oFD = (size_t)l * FF * DD;

        // --- TimeMix ---
        if (l > 0) {
            rms_kernel<<<MM, blk>>>(h, nullptr, ln1 + l * DD, xnh, xnl);
            gemm_hmma<<<gD, gblk, SMEM>>>(xnh, xnl, wrh + oDD, wrl + oDD, r,
                                          nullptr, nullptr, nullptr, DD, DD, 1);
        }
        gemm_hmma<<<gD, gblk, SMEM>>>(xnh, xnl, wkh + oDD, wkl + oDD, k,
                                      nullptr, nullptr, nullptr, DD, DD, 0);
        gemm_hmma<<<gD, gblk, SMEM>>>(xnh, xnl, wvh + oDD, wvl + oDD, v,
                                      nullptr, nullptr, nullptr, DD, DD, 0);
        timemix_kernel<<<(BB * DD) / 256, blk>>>(k, v, decay + l * DD, st);
        rms_kernel<<<MM, blk>>>(st, r, lnx + l * DD, xnh, xnl);
        gemm_hmma<<<gD, gblk, SMEM>>>(xnh, xnl, woh + oDD, wol + oDD, h,
                                      nullptr, nullptr, nullptr, DD, DD, 2);

        // --- ChannelMix (gate fused into W2 epilogue) ---
        rms_kernel<<<MM, blk>>>(h, nullptr, ln2 + l * DD, xnh, xnl);
        gemm_hmma<<<gF, gblk, SMEM>>>(xnh, xnl, w1h + oFD, w1l + oFD, g1,
                                      nullptr, nullptr, nullptr, FF, DD, 0);
        gemm_hmma<<<gF, gblk, SMEM>>>(xnh, xnl, w2h + oFD, w2l + oFD, nullptr,
                                      g1, gh, gl, FF, DD, 3);
        gemm_hmma<<<gD, gblk, SMEM>>>(gh, gl, o2h + oFD, o2l + oFD, h,
                                      nullptr, nullptr, nullptr, DD, FF, 2);
    }

    // --- tied head ---
    rms_kernel<<<MM, blk>>>(h, nullptr, ln_out, xnh, xnl);
    gemm_hmma<<<gH, gblk, SMEM>>>(xnh, xnl, eh, el, out,
                                  nullptr, nullptr, nullptr, VV, DD, 0);
}

// round 15
// speedup vs baseline: 1.3485x; 1.0836x over previous
#include <cuda_runtime.h>
#include <cuda_bf16.h>
#include <stdint.h>
#include <math.h>

#define BB 8
#define TT 256
#define DD 1024
#define LL 12
#define FF 4096
#define VV 32000
#define MM (BB*TT)   // 2048 rows
#define NSEG 8
#define SEGLEN (TT/NSEG)

// ======================= scratch (static device globals; no runtime alloc) =======================
__device__ __align__(256) float g_h [MM*DD];
__device__ __align__(256) float g_r [MM*DD];
__device__ __align__(256) float g_k [MM*DD];
__device__ __align__(256) float g_v [MM*DD];
__device__ __align__(256) float g_st[MM*DD];
__device__ __align__(256) float g_g1[MM*FF];
__device__ __align__(256) float g_part[BB*NSEG*DD];

__device__ __align__(256) __nv_bfloat16 g_xnh[MM*DD], g_xnl[MM*DD];
__device__ __align__(256) __nv_bfloat16 g_gh [MM*FF], g_gl [MM*FF];

// fused QKV weights: per layer, rows [0,1024)=Wr, [1024,2048)=Wk, [2048,3072)=Wv
__device__ __align__(256) __nv_bfloat16 g_qkvh[LL*3*DD*DD], g_qkvl[LL*3*DD*DD];
__device__ __align__(256) __nv_bfloat16 g_woh[LL*DD*DD], g_wol[LL*DD*DD];
__device__ __align__(256) __nv_bfloat16 g_w1h[LL*FF*DD], g_w1l[LL*FF*DD];
__device__ __align__(256) __nv_bfloat16 g_w2h[LL*FF*DD], g_w2l[LL*FF*DD];
__device__ __align__(256) __nv_bfloat16 g_o2h[LL*DD*FF], g_o2l[LL*DD*FF];
__device__ __align__(256) __nv_bfloat16 g_eh [VV*DD],    g_el [VV*DD];

// ======================= split helpers (hi = trunc bf16, lo = rn bf16 of remainder) ==========
__device__ __forceinline__ void split4(float4 v, uint2& hi, uint2& lo) {
    uint32_t h01 = __byte_perm(__float_as_uint(v.x), __float_as_uint(v.y), 0x7632);
    uint32_t h23 = __byte_perm(__float_as_uint(v.z), __float_as_uint(v.w), 0x7632);
    float lx = v.x - __uint_as_float(__float_as_uint(v.x) & 0xffff0000u);
    float ly = v.y - __uint_as_float(__float_as_uint(v.y) & 0xffff0000u);
    float lz = v.z - __uint_as_float(__float_as_uint(v.z) & 0xffff0000u);
    float lw = v.w - __uint_as_float(__float_as_uint(v.w) & 0xffff0000u);
    __nv_bfloat162 p01 = __floats2bfloat162_rn(lx, ly);
    __nv_bfloat162 p23 = __floats2bfloat162_rn(lz, lw);
    hi = make_uint2(h01, h23);
    lo = make_uint2(*reinterpret_cast<uint32_t*>(&p01), *reinterpret_cast<uint32_t*>(&p23));
}

__device__ __forceinline__ void split2(float2 v, uint32_t& h, uint32_t& l) {
    h = __byte_perm(__float_as_uint(v.x), __float_as_uint(v.y), 0x7632);
    float lx = v.x - __uint_as_float(__float_as_uint(v.x) & 0xffff0000u);
    float ly = v.y - __uint_as_float(__float_as_uint(v.y) & 0xffff0000u);
    __nv_bfloat162 p = __floats2bfloat162_rn(lx, ly);
    l = *reinterpret_cast<uint32_t*>(&p);
}

// generic split: 2 float4 per thread for MLP
__global__ void split_kernel(const float* __restrict__ src, __nv_bfloat16* __restrict__ hi,
                             __nv_bfloat16* __restrict__ lo) {
    size_t i = ((size_t)blockIdx.x * blockDim.x + threadIdx.x) * 2;
    float4 v0 = ((const float4*)src)[i];
    float4 v1 = ((const float4*)src)[i + 1];
    uint2 h0, l0, h1, l1;
    split4(v0, h0, l0);
    split4(v1, h1, l1);
    ((uint2*)hi)[i]     = h0;
    ((uint2*)lo)[i]     = l0;
    ((uint2*)hi)[i + 1] = h1;
    ((uint2*)lo)[i + 1] = l1;
}

// QKV split: packs Wr/Wk/Wv into fused [L][3*DD][DD] layout; 2 float4 per thread
__global__ void qkv_split_kernel(const float* __restrict__ Wr, const float* __restrict__ Wk,
                                 const float* __restrict__ Wv,
                                 __nv_bfloat16* __restrict__ qh, __nv_bfloat16* __restrict__ ql) {
    size_t i = ((size_t)blockIdx.x * blockDim.x + threadIdx.x) * 2;
    #pragma unroll
    for (int e = 0; e < 2; ++e) {
        size_t ii = i + e;                 // dst float4 index
        int dstrow = (int)(ii >> 8);       // DD/4 = 256 float4 per row
        int l   = dstrow / (3 * DD);
        int rem = dstrow - l * 3 * DD;
        int w   = rem >> 10;               // 0=Wr 1=Wk 2=Wv
        int rr  = rem & 1023;
        const float* src = (w == 0) ? Wr : (w == 1) ? Wk : Wv;
        float4 v = ((const float4*)src)[((size_t)l * DD + rr) * 256 + (ii & 255)];
        uint2 h, lo2;
        split4(v, h, lo2);
        ((uint2*)qh)[ii] = h;
        ((uint2*)ql)[ii] = lo2;
    }
}

// ======================= aux kernels =======================
__device__ __forceinline__ float block_reduce_sum_256(float val) {
    #pragma unroll
    for (int o = 16; o > 0; o >>= 1) val += __shfl_xor_sync(0xffffffffu, val, o);
    __shared__ float sh[8];
    __shared__ float s_tot;
    int w = threadIdx.x >> 5;
    if ((threadIdx.x & 31) == 0) sh[w] = val;
    __syncthreads();
    if (threadIdx.x < 8) {
        float v2 = sh[threadIdx.x];
        #pragma unroll
        for (int o = 4; o > 0; o >>= 1) v2 += __shfl_xor_sync(0xffu, v2, o);
        if (threadIdx.x == 0) s_tot = v2;
    }
    __syncthreads();
    return s_tot;
}
__device__ __forceinline__ float sigmoidf_(float x) { return 1.0f / (1.0f + expf(-x)); }

// embedding gather + RMSNorm -> f32 h (residual stream)
__global__ void embed_rms_kernel(const int* __restrict__ x, const float* __restrict__ embed,
                                 const float* __restrict__ w, float* __restrict__ out) {
    int row = blockIdx.x;
    int tok = x[row];
    int t = threadIdx.x;
    float4 v = ((const float4*)(embed + (size_t)tok * DD))[t];
    float ss = v.x*v.x + v.y*v.y + v.z*v.z + v.w*v.w;
    float tot = block_reduce_sum_256(ss);
    float s = rsqrtf(tot / (float)DD + 1e-6f);
    float4 wv = ((const float4*)w)[t];
    float4 o = make_float4(v.x*s*wv.x, v.y*s*wv.y, v.z*s*wv.z, v.w*s*wv.w);
    ((float4*)(out + (size_t)row * DD))[t] = o;
}

// RMSNorm (optional elementwise gate) -> bf16 hi/lo planes (feeds GEMM A)
__global__ void rms_kernel(const float* __restrict__ x, const float* __restrict__ gate,
                           const float* __restrict__ w,
                           __nv_bfloat16* __restrict__ oh, __nv_bfloat16* __restrict__ ol) {
    int row = blockIdx.x;
    int t = threadIdx.x;
    float4 v = ((const float4*)(x + (size_t)row * DD))[t];
    if (gate != nullptr) {
        float4 g = ((const float4*)(gate + (size_t)row * DD))[t];
        v.x *= g.x; v.y *= g.y; v.z *= g.z; v.w *= g.w;
    }
    float ss = v.x*v.x + v.y*v.y + v.z*v.z + v.w*v.w;
    float tot = block_reduce_sum_256(ss);
    float s = rsqrtf(tot / (float)DD + 1e-6f);
    float4 wv = ((const float4*)w)[t];
    float4 o = make_float4(v.x*s*wv.x, v.y*s*wv.y, v.z*s*wv.z, v.w*s*wv.w);
    uint2 h, l;
    split4(o, h, l);
    ((uint2*)(oh + (size_t)row * DD))[t] = h;
    ((uint2*)(ol + (size_t)row * DD))[t] = l;
}

// TimeMix recurrence, parallelized over NSEG segments (exact per-segment ordering,
// prefix regrouped across segments).
// idx = (b*NSEG + s)*DD + e
__global__ void timemix_part(const float* __restrict__ k, const float* __restrict__ v,
                             const float* __restrict__ decay, float* __restrict__ part) {
    int idx = blockIdx.x * blockDim.x + threadIdx.x;
    int e  = idx & (DD - 1);
    int bs = idx >> 10;
    int s  = bs & (NSEG - 1);
    int b  = bs >> 3;
    float dec = sigmoidf_(decay[e]);
    float ln  = logf(fmaxf(dec, 1e-7f));
    size_t base = (size_t)b * TT * DD + e;
    float sum = 0.0f;
    int t0 = s * SEGLEN;
    #pragma unroll 4
    for (int j = 0; j < SEGLEN; ++j) {
        int t = t0 + j;
        float kv = k[base + (size_t)t * DD] * v[base + (size_t)t * DD];
        float sc = expf((float)t * ln);
        sum += kv / fmaxf(sc, 1e-10f);
    }
    part[idx] = sum;
}

__global__ void timemix_apply(const float* __restrict__ k, const float* __restrict__ v,
                              const float* __restrict__ decay, const float* __restrict__ part,
                              float* __restrict__ state) {
    int idx = blockIdx.x * blockDim.x + threadIdx.x;
    int e  = idx & (DD - 1);
    int bs = idx >> 10;
    int s  = bs & (NSEG - 1);
    int b  = bs >> 3;
    float dec = sigmoidf_(decay[e]);
    float ln  = logf(fmaxf(dec, 1e-7f));
    size_t base = (size_t)b * TT * DD + e;
    float cum = 0.0f;
    for (int s2 = 0; s2 < s; ++s2)
        cum += part[((b * NSEG + s2) << 10) + e];
    int t0 = s * SEGLEN;
    #pragma unroll 4
    for (int j = 0; j < SEGLEN; ++j) {
        int t = t0 + j;
        float kv = k[base + (size_t)t * DD] * v[base + (size_t)t * DD];
        float sc = expf((float)t * ln);
        cum += kv / fmaxf(sc, 1e-10f);
        state[base + (size_t)t * DD] = cum * sc;
    }
}

// ======================= common GEMM macros =======================
#define SWZ(x) ((x) ^ (((x) >> 3) & 0x70))

#define LDSM4(r, addr) \
    asm volatile("ldmatrix.sync.aligned.m8n8.x4.shared.b16 {%0,%1,%2,%3}, [%4];" \
        : "=r"((r)[0]), "=r"((r)[1]), "=r"((r)[2]), "=r"((r)[3]) : "r"(addr))

#define MMA16816(d, a, b0, b1) \
    asm volatile("mma.sync.aligned.m16n8k16.row.col.f32.bf16.bf16.f32 " \
        "{%0,%1,%2,%3}, {%4,%5,%6,%7}, {%8,%9}, {%0,%1,%2,%3};" \
        : "+f"((d)[0]), "+f"((d)[1]), "+f"((d)[2]), "+f"((d)[3]) \
        : "r"((a)[0]), "r"((a)[1]), "r"((a)[2]), "r"((a)[3]), "r"(b0), "r"(b1))

#define CP_ASYNC16(dst, src) \
    asm volatile("{ .reg .u64 g; cvta.to.global.u64 g, %1; cp.async.cg.shared.global [%0], [g], 16; }" \
        :: "r"(dst), "l"(src) : "memory")
#define CP_COMMIT() asm volatile("cp.async.commit_group;" ::: "memory")
#define CP_WAIT2()  asm volatile("cp.async.wait_group 2;" ::: "memory")
#define CP_WAIT1()  asm volatile("cp.async.wait_group 1;" ::: "memory")
#define CP_WAIT0()  asm volatile("cp.async.wait_group 0;" ::: "memory")

__device__ __forceinline__ uint32_t smem_u32(const void* p) {
    uint32_t a;
    asm("{ .reg .u64 t; cvta.to.shared.u64 t, %1; cvt.u32.u64 %0, t; }" : "=r"(a) : "l"(p));
    return a;
}

// ======================= GEMM: CTA 128x128, 1024 thr, 32 warps (4M x 8N), warp 32x16 ======
// Single-barrier 3-stage cp.async pipeline (R12-verified core).
// Fragment layout: LDSM4 -> {n0k0, n0k1, n1k0, n1k1}; B pair for n-sub s = (r[2s], r[2s+1]).
// epi: 0 = store f32, 1 = sigmoid, 2 = residual add,
//      3 = fused gate: out = silu(G) * acc -> split bf16 to OH/OL,
//      4 = QKV route: c<1024 -> sigmoid->C(r); c<2048 -> D2(k); else D3(v). Row stride DD.
#define PLANE 16384
#define STAGE128 65536   // 4 planes x 128 rows x 128B
#define NST128 3

__global__ void __launch_bounds__(1024)
gemm_hmma(const __nv_bfloat16* __restrict__ Ah, const __nv_bfloat16* __restrict__ Al,
          const __nv_bfloat16* __restrict__ Bh, const __nv_bfloat16* __restrict__ Bl,
          float* __restrict__ C, const float* __restrict__ G,
          __nv_bfloat16* __restrict__ OH, __nv_bfloat16* __restrict__ OL,
          float* __restrict__ D2, float* __restrict__ D3,
          int N, int K, int epi) {
    extern __shared__ __align__(1024) char smem[];
    const uint32_t sb = smem_u32(smem);
    const int tid  = threadIdx.x;
    const int lane = tid & 31, wid = tid >> 5;
    const int wm = wid & 3;          // m offset wm*32
    const int wn = wid >> 2;         // 0..7 -> n offset wn*16
    const int bm = blockIdx.y * 128, bn = blockIdx.x * 128;

    // cp.async: 8 threads per 128B row per plane; 1x16B each
    const int lr = tid >> 3;
    const int lq = tid & 7;
    const __nv_bfloat16* psrc[4] = {
        Ah + (size_t)(bm + lr) * K + lq * 8,
        Al + (size_t)(bm + lr) * K + lq * 8,
        Bh + (size_t)(bn + lr) * K + lq * 8,
        Bl + (size_t)(bn + lr) * K + lq * 8
    };
    const uint32_t dsw = SWZ((uint32_t)(lr * 128 + lq * 16));

    const uint32_t aoff0 = (uint32_t)(wm * 32 + (lane & 15)) * 128 + (lane >> 4) * 16;
    const uint32_t boff0 = (uint32_t)(wn * 16 + ((lane >> 4) & 1) * 8 + (lane & 7)) * 128
                         + ((lane >> 3) & 1) * 16;

    float acc[2][2][4];
    #pragma unroll
    for (int mt = 0; mt < 2; ++mt)
        #pragma unroll
        for (int nt = 0; nt < 2; ++nt)
            #pragma unroll
            for (int q = 0; q < 4; ++q) acc[mt][nt][q] = 0.0f;

    const int nch = K >> 6;

    // prologue: chunks 0,1,2 into stages 0,1,2
    #pragma unroll
    for (int s = 0; s < 3; ++s) {
        const uint32_t st = sb + s * STAGE128;
        const int koff = s * 64;
        #pragma unroll
        for (int p = 0; p < 4; ++p)
            CP_ASYNC16(st + p * PLANE + dsw, psrc[p] + koff);
        CP_COMMIT();
    }
    CP_WAIT2();        // chunk 0 arrived
    __syncthreads();

    int buf = 0;
    for (int ch = 0; ch < nch; ++ch) {
        const uint32_t st = sb + buf * STAGE128;
        #pragma unroll
        for (int kk = 0; kk < 4; ++kk) {
            uint32_t ah[2][4], al[2][4], bh[4], bl[4];
            #pragma unroll
            for (int mt = 0; mt < 2; ++mt) {
                uint32_t o = SWZ(aoff0 + mt * 2048 + kk * 32);
                LDSM4(ah[mt], st + o);
                LDSM4(al[mt], st + PLANE + o);
            }
            {
                uint32_t o = SWZ(boff0 + kk * 32);
                LDSM4(bh, st + 2 * PLANE + o);
                LDSM4(bl, st + 3 * PLANE + o);
            }
            #pragma unroll
            for (int mt = 0; mt < 2; ++mt)
                #pragma unroll
                for (int nt = 0; nt < 2; ++nt)
                    MMA16816(acc[mt][nt], ah[mt], bh[nt * 2], bh[nt * 2 + 1]);
            #pragma unroll
            for (int mt = 0; mt < 2; ++mt)
                #pragma unroll
                for (int nt = 0; nt < 2; ++nt)
                    MMA16816(acc[mt][nt], ah[mt], bl[nt * 2], bl[nt * 2 + 1]);
            #pragma unroll
            for (int mt = 0; mt < 2; ++mt)
                #pragma unroll
                for (int nt = 0; nt < 2; ++nt)
                    MMA16816(acc[mt][nt], al[mt], bh[nt * 2], bh[nt * 2 + 1]);
        }
        // wait for chunk ch+1 (issued >= 1 iteration ago)
        if (ch + 2 < nch)      CP_WAIT1();
        else if (ch + 1 < nch) CP_WAIT0();
        __syncthreads();   // (a) all warps done with buf; (b) chunk ch+1 visible
        if (ch + 3 < nch) {
            const int koff = (ch + 3) * 64;
            #pragma unroll
            for (int p = 0; p < 4; ++p)
                CP_ASYNC16(st + p * PLANE + dsw, psrc[p] + koff);
            CP_COMMIT();
        }
        ++buf; if (buf == NST128) buf = 0;
    }

    // epilogue
    const int g  = lane >> 2;
    const int tc = lane & 3;
    #pragma unroll
    for (int mt = 0; mt < 2; ++mt) {
        #pragma unroll
        for (int nt = 0; nt < 2; ++nt) {
            const int r0 = bm + wm * 32 + mt * 16 + g;
            const int c  = bn + wn * 16 + nt * 8 + tc * 2;
            float2 v0 = make_float2(acc[mt][nt][0], acc[mt][nt][1]);
            float2 v1 = make_float2(acc[mt][nt][2], acc[mt][nt][3]);
            if (epi == 4) {
                const int c2 = c & 1023;
                float* dst;
                if (c < 1024) {
                    v0.x = sigmoidf_(v0.x); v0.y = sigmoidf_(v0.y);
                    v1.x = sigmoidf_(v1.x); v1.y = sigmoidf_(v1.y);
                    dst = C;
                } else if (c < 2048) {
                    dst = D2;
                } else {
                    dst = D3;
                }
                *(float2*)(dst + (size_t)r0 * DD + c2)       = v0;
                *(float2*)(dst + (size_t)(r0 + 8) * DD + c2) = v1;
            } else if (epi == 3) {
                const float2 q0 = *(const float2*)(G + (size_t)r0 * N + c);
                const float2 q1 = *(const float2*)(G + (size_t)(r0 + 8) * N + c);
                v0.x *= q0.x * sigmoidf_(q0.x); v0.y *= q0.y * sigmoidf_(q0.y);
                v1.x *= q1.x * sigmoidf_(q1.x); v1.y *= q1.y * sigmoidf_(q1.y);
                uint32_t h0, l0, h1, l1;
                split2(v0, h0, l0);
                split2(v1, h1, l1);
                *(uint32_t*)(OH + (size_t)r0 * N + c)       = h0;
                *(uint32_t*)(OL + (size_t)r0 * N + c)       = l0;
                *(uint32_t*)(OH + (size_t)(r0 + 8) * N + c) = h1;
                *(uint32_t*)(OL + (size_t)(r0 + 8) * N + c) = l1;
            } else {
                float* p0 = C + (size_t)r0 * N + c;
                float* p1 = C + (size_t)(r0 + 8) * N + c;
                if (epi == 1) {
                    v0.x = sigmoidf_(v0.x); v0.y = sigmoidf_(v0.y);
                    v1.x = sigmoidf_(v1.x); v1.y = sigmoidf_(v1.y);
                } else if (epi == 2) {
                    float2 c0 = *(const float2*)p0;
                    float2 c1 = *(const float2*)p1;
                    v0.x += c0.x; v0.y += c0.y;
                    v1.x += c1.x; v1.y += c1.y;
                }
                *(float2*)p0 = v0;
                *(float2*)p1 = v1;
            }
        }
    }
}

// ======================= launch =======================
extern "C" void kernel_launch(void* const* d_in, const int* in_sizes, int n_in,
                              void* d_out, int out_size) {
    const int*   x      = (const int*)  d_in[0];
    const float* embed  = (const float*)d_in[1];
    const float* ln_in  = (const float*)d_in[2];
    const float* ln_out = (const float*)d_in[3];
    const float* ln1    = (const float*)d_in[4];
    const float* Wr     = (const float*)d_in[5];
    const float* Wk     = (const float*)d_in[6];
    const float* Wv     = (const float*)d_in[7];
    const float* Wo     = (const float*)d_in[8];
    const float* decay  = (const float*)d_in[9];
    const float* lnx    = (const float*)d_in[10];
    const float* ln2    = (const float*)d_in[11];
    const float* W1     = (const float*)d_in[12];
    const float* W2     = (const float*)d_in[13];
    const float* Wo2    = (const float*)d_in[14];
    float* out = (float*)d_out;

    float *h, *r, *k, *v, *st, *g1, *part;
    __nv_bfloat16 *xnh, *xnl, *gh, *gl;
    __nv_bfloat16 *qkvh, *qkvl, *woh, *wol;
    __nv_bfloat16 *w1h, *w1l, *w2h, *w2l, *o2h, *o2l, *eh, *el;
    cudaGetSymbolAddress((void**)&h,  g_h);   cudaGetSymbolAddress((void**)&r,  g_r);
    cudaGetSymbolAddress((void**)&k,  g_k);   cudaGetSymbolAddress((void**)&v,  g_v);
    cudaGetSymbolAddress((void**)&st, g_st);  cudaGetSymbolAddress((void**)&g1, g_g1);
    cudaGetSymbolAddress((void**)&part, g_part);
    cudaGetSymbolAddress((void**)&xnh, g_xnh); cudaGetSymbolAddress((void**)&xnl, g_xnl);
    cudaGetSymbolAddress((void**)&gh,  g_gh);  cudaGetSymbolAddress((void**)&gl,  g_gl);
    cudaGetSymbolAddress((void**)&qkvh, g_qkvh); cudaGetSymbolAddress((void**)&qkvl, g_qkvl);
    cudaGetSymbolAddress((void**)&woh, g_woh); cudaGetSymbolAddress((void**)&wol, g_wol);
    cudaGetSymbolAddress((void**)&w1h, g_w1h); cudaGetSymbolAddress((void**)&w1l, g_w1l);
    cudaGetSymbolAddress((void**)&w2h, g_w2h); cudaGetSymbolAddress((void**)&w2l, g_w2l);
    cudaGetSymbolAddress((void**)&o2h, g_o2h); cudaGetSymbolAddress((void**)&o2l, g_o2l);
    cudaGetSymbolAddress((void**)&eh,  g_eh);  cudaGetSymbolAddress((void**)&el,  g_el);

    const int SMEM = NST128 * STAGE128;   // 196608
    cudaFuncSetAttribute(gemm_hmma, cudaFuncAttributeMaxDynamicSharedMemorySize, SMEM);

    const dim3 blk(256);
    const dim3 gblk(1024);
    const dim3 gQKV(3 * DD / 128, MM / 128);  // 24 x 16 = 384 CTAs
    const dim3 gD(DD / 128, MM / 128);        // 8 x 16
    const dim3 gF(FF / 128, MM / 128);        // 32 x 16
    const dim3 gH(VV / 128, MM / 128);        // 250 x 16
    const int TMGRID = (BB * DD * NSEG) / 256;

    // ---- launch order: my index 3 = QKV-GEMM (profiled) ----
    qkv_split_kernel<<<(3*LL*DD*DD)/2048, blk>>>(Wr, Wk, Wv, qkvh, qkvl);   // #0
    embed_rms_kernel<<<MM, blk>>>(x, embed, ln_in, h);                      // #1
    rms_kernel<<<MM, blk>>>(h, nullptr, ln1, xnh, xnl);                     // #2
    gemm_hmma<<<gQKV, gblk, SMEM>>>(xnh, xnl, qkvh, qkvl, r,
                                    nullptr, nullptr, nullptr, k, v,
                                    3 * DD, DD, 4);                          // #3 <-- profiled

    // remaining splits (2 float4/thread)
    split_kernel<<<(LL*DD*DD)/2048, blk>>>(Wo,  woh, wol);
    split_kernel<<<(LL*FF*DD)/2048, blk>>>(W1,  w1h, w1l);
    split_kernel<<<(LL*FF*DD)/2048, blk>>>(W2,  w2h, w2l);
    split_kernel<<<(LL*DD*FF)/2048, blk>>>(Wo2, o2h, o2l);
    split_kernel<<<(VV*DD)/2048,    blk>>>(embed, eh, el);

    for (int l = 0; l < LL; ++l) {
        const size_t oQ  = (size_t)l * 3 * DD * DD;
        const size_t oDD = (size_t)l * DD * DD;
        const size_t oFD = (size_t)l * FF * DD;

        // --- TimeMix ---
        if (l > 0) {
            rms_kernel<<<MM, blk>>>(h, nullptr, ln1 + l * DD, xnh, xnl);
            gemm_hmma<<<gQKV, gblk, SMEM>>>(xnh, xnl, qkvh + oQ, qkvl + oQ, r,
                                            nullptr, nullptr, nullptr, k, v,
                                            3 * DD, DD, 4);
        }
        timemix_part <<<TMGRID, blk>>>(k, v, decay + l * DD, part);
        timemix_apply<<<TMGRID, blk>>>(k, v, decay + l * DD, part, st);
        rms_kernel<<<MM, blk>>>(st, r, lnx + l * DD, xnh, xnl);
        gemm_hmma<<<gD, gblk, SMEM>>>(xnh, xnl, woh + oDD, wol + oDD, h,
                                      nullptr, nullptr, nullptr, nullptr, nullptr, DD, DD, 2);

        // --- ChannelMix (gate fused into W2 epilogue) ---
        rms_kernel<<<MM, blk>>>(h, nullptr, ln2 + l * DD, xnh, xnl);
        gemm_hmma<<<gF, gblk, SMEM>>>(xnh, xnl, w1h + oFD, w1l + oFD, g1,
                                      nullptr, nullptr, nullptr, nullptr, nullptr, FF, DD, 0);
        gemm_hmma<<<gF, gblk, SMEM>>>(xnh, xnl, w2h + oFD, w2l + oFD, nullptr,
                                      g1, gh, gl, nullptr, nullptr, FF, DD, 3);
        gemm_hmma<<<gD, gblk, SMEM>>>(gh, gl, o2h + oFD, o2l + oFD, h,
                                      nullptr, nullptr, nullptr, nullptr, nullptr, DD, FF, 2);
    }

    // --- tied head ---
    rms_kernel<<<MM, blk>>>(h, nullptr, ln_out, xnh, xnl);
    gemm_hmma<<<gH, gblk, SMEM>>>(xnh, xnl, eh, el, out,
                                  nullptr, nullptr, nullptr, nullptr, nullptr, VV, DD, 0);
}

// round 16
// speedup vs baseline: 1.4201x; 1.0531x over previous
#include <cuda_runtime.h>
#include <cuda_bf16.h>
#include <stdint.h>
#include <math.h>

#define BB 8
#define TT 256
#define DD 1024
#define LL 12
#define FF 4096
#define VV 32000
#define MM (BB*TT)   // 2048 rows
#define NSEG 8
#define SEGLEN (TT/NSEG)

// ======================= scratch (static device globals; no runtime alloc) =======================
__device__ __align__(256) float g_h [MM*DD];
__device__ __align__(256) float g_r [MM*DD];
__device__ __align__(256) float g_k [MM*DD];
__device__ __align__(256) float g_v [MM*DD];
__device__ __align__(256) float g_st[MM*DD];
__device__ __align__(256) float g_part[BB*NSEG*DD];

__device__ __align__(256) __nv_bfloat16 g_xnh[MM*DD], g_xnl[MM*DD];
__device__ __align__(256) __nv_bfloat16 g_gh [MM*FF], g_gl [MM*FF];

// fused QKV weights: per layer, rows [0,1024)=Wr, [1024,2048)=Wk, [2048,3072)=Wv
__device__ __align__(256) __nv_bfloat16 g_qkvh[LL*3*DD*DD], g_qkvl[LL*3*DD*DD];
// fused W1/W2 weights, interleaved: per layer, row 2j = W1 row j, row 2j+1 = W2 row j
__device__ __align__(256) __nv_bfloat16 g_w12h[LL*2*FF*DD], g_w12l[LL*2*FF*DD];
__device__ __align__(256) __nv_bfloat16 g_woh[LL*DD*DD], g_wol[LL*DD*DD];
__device__ __align__(256) __nv_bfloat16 g_o2h[LL*DD*FF], g_o2l[LL*DD*FF];
__device__ __align__(256) __nv_bfloat16 g_eh [VV*DD],    g_el [VV*DD];

// ======================= split helpers (hi = trunc bf16, lo = rn bf16 of remainder) ==========
__device__ __forceinline__ void split4(float4 v, uint2& hi, uint2& lo) {
    uint32_t h01 = __byte_perm(__float_as_uint(v.x), __float_as_uint(v.y), 0x7632);
    uint32_t h23 = __byte_perm(__float_as_uint(v.z), __float_as_uint(v.w), 0x7632);
    float lx = v.x - __uint_as_float(__float_as_uint(v.x) & 0xffff0000u);
    float ly = v.y - __uint_as_float(__float_as_uint(v.y) & 0xffff0000u);
    float lz = v.z - __uint_as_float(__float_as_uint(v.z) & 0xffff0000u);
    float lw = v.w - __uint_as_float(__float_as_uint(v.w) & 0xffff0000u);
    __nv_bfloat162 p01 = __floats2bfloat162_rn(lx, ly);
    __nv_bfloat162 p23 = __floats2bfloat162_rn(lz, lw);
    hi = make_uint2(h01, h23);
    lo = make_uint2(*reinterpret_cast<uint32_t*>(&p01), *reinterpret_cast<uint32_t*>(&p23));
}

__device__ __forceinline__ void split1(float x, uint16_t& h, uint16_t& l) {
    uint32_t xi = __float_as_uint(x);
    h = (uint16_t)(xi >> 16);
    float lo = x - __uint_as_float(xi & 0xffff0000u);
    __nv_bfloat16 lb = __float2bfloat16_rn(lo);
    l = *reinterpret_cast<uint16_t*>(&lb);
}

// generic split: 2 float4 per thread
__global__ void split_kernel(const float* __restrict__ src, __nv_bfloat16* __restrict__ hi,
                             __nv_bfloat16* __restrict__ lo) {
    size_t i = ((size_t)blockIdx.x * blockDim.x + threadIdx.x) * 2;
    float4 v0 = ((const float4*)src)[i];
    float4 v1 = ((const float4*)src)[i + 1];
    uint2 h0, l0, h1, l1;
    split4(v0, h0, l0);
    split4(v1, h1, l1);
    ((uint2*)hi)[i]     = h0;
    ((uint2*)lo)[i]     = l0;
    ((uint2*)hi)[i + 1] = h1;
    ((uint2*)lo)[i + 1] = l1;
}

// QKV split: packs Wr/Wk/Wv into fused [L][3*DD][DD] layout; 2 float4 per thread
__global__ void qkv_split_kernel(const float* __restrict__ Wr, const float* __restrict__ Wk,
                                 const float* __restrict__ Wv,
                                 __nv_bfloat16* __restrict__ qh, __nv_bfloat16* __restrict__ ql) {
    size_t i = ((size_t)blockIdx.x * blockDim.x + threadIdx.x) * 2;
    #pragma unroll
    for (int e = 0; e < 2; ++e) {
        size_t ii = i + e;                 // dst float4 index
        int dstrow = (int)(ii >> 8);       // DD/4 = 256 float4 per row
        int l   = dstrow / (3 * DD);
        int rem = dstrow - l * 3 * DD;
        int w   = rem >> 10;               // 0=Wr 1=Wk 2=Wv
        int rr  = rem & 1023;
        const float* src = (w == 0) ? Wr : (w == 1) ? Wk : Wv;
        float4 v = ((const float4*)src)[((size_t)l * DD + rr) * 256 + (ii & 255)];
        uint2 h, lo2;
        split4(v, h, lo2);
        ((uint2*)qh)[ii] = h;
        ((uint2*)ql)[ii] = lo2;
    }
}

// W12 split: packs W1/W2 into fused [L][2*FF][DD] interleaved layout; 2 float4 per thread
__global__ void w12_split_kernel(const float* __restrict__ W1, const float* __restrict__ W2,
                                 __nv_bfloat16* __restrict__ qh, __nv_bfloat16* __restrict__ ql) {
    size_t i = ((size_t)blockIdx.x * blockDim.x + threadIdx.x) * 2;
    #pragma unroll
    for (int e = 0; e < 2; ++e) {
        size_t ii = i + e;                 // dst float4 index
        int dstrow = (int)(ii >> 8);       // 256 float4 per 1024-row
        int l   = dstrow / (2 * FF);
        int rem = dstrow - l * 2 * FF;
        int j   = rem >> 1;
        int s   = rem & 1;                 // 0 = W1, 1 = W2
        const float* src = s ? W2 : W1;
        float4 v = ((const float4*)src)[((size_t)l * FF + j) * 256 + (ii & 255)];
        uint2 h, lo2;
        split4(v, h, lo2);
        ((uint2*)qh)[ii] = h;
        ((uint2*)ql)[ii] = lo2;
    }
}

// ======================= aux kernels =======================
__device__ __forceinline__ float block_reduce_sum_256(float val) {
    #pragma unroll
    for (int o = 16; o > 0; o >>= 1) val += __shfl_xor_sync(0xffffffffu, val, o);
    __shared__ float sh[8];
    __shared__ float s_tot;
    int w = threadIdx.x >> 5;
    if ((threadIdx.x & 31) == 0) sh[w] = val;
    __syncthreads();
    if (threadIdx.x < 8) {
        float v2 = sh[threadIdx.x];
        #pragma unroll
        for (int o = 4; o > 0; o >>= 1) v2 += __shfl_xor_sync(0xffu, v2, o);
        if (threadIdx.x == 0) s_tot = v2;
    }
    __syncthreads();
    return s_tot;
}
__device__ __forceinline__ float sigmoidf_(float x) { return 1.0f / (1.0f + expf(-x)); }

// embedding gather + RMSNorm -> f32 h (residual stream)
__global__ void embed_rms_kernel(const int* __restrict__ x, const float* __restrict__ embed,
                                 const float* __restrict__ w, float* __restrict__ out) {
    int row = blockIdx.x;
    int tok = x[row];
    int t = threadIdx.x;
    float4 v = ((const float4*)(embed + (size_t)tok * DD))[t];
    float ss = v.x*v.x + v.y*v.y + v.z*v.z + v.w*v.w;
    float tot = block_reduce_sum_256(ss);
    float s = rsqrtf(tot / (float)DD + 1e-6f);
    float4 wv = ((const float4*)w)[t];
    float4 o = make_float4(v.x*s*wv.x, v.y*s*wv.y, v.z*s*wv.z, v.w*s*wv.w);
    ((float4*)(out + (size_t)row * DD))[t] = o;
}

// RMSNorm (optional elementwise gate) -> bf16 hi/lo planes (feeds GEMM A)
__global__ void rms_kernel(const float* __restrict__ x, const float* __restrict__ gate,
                           const float* __restrict__ w,
                           __nv_bfloat16* __restrict__ oh, __nv_bfloat16* __restrict__ ol) {
    int row = blockIdx.x;
    int t = threadIdx.x;
    float4 v = ((const float4*)(x + (size_t)row * DD))[t];
    if (gate != nullptr) {
        float4 g = ((const float4*)(gate + (size_t)row * DD))[t];
        v.x *= g.x; v.y *= g.y; v.z *= g.z; v.w *= g.w;
    }
    float ss = v.x*v.x + v.y*v.y + v.z*v.z + v.w*v.w;
    float tot = block_reduce_sum_256(ss);
    float s = rsqrtf(tot / (float)DD + 1e-6f);
    float4 wv = ((const float4*)w)[t];
    float4 o = make_float4(v.x*s*wv.x, v.y*s*wv.y, v.z*s*wv.z, v.w*s*wv.w);
    uint2 h, l;
    split4(o, h, l);
    ((uint2*)(oh + (size_t)row * DD))[t] = h;
    ((uint2*)(ol + (size_t)row * DD))[t] = l;
}

// TimeMix recurrence, parallelized over NSEG segments
__global__ void timemix_part(const float* __restrict__ k, const float* __restrict__ v,
                             const float* __restrict__ decay, float* __restrict__ part) {
    int idx = blockIdx.x * blockDim.x + threadIdx.x;
    int e  = idx & (DD - 1);
    int bs = idx >> 10;
    int s  = bs & (NSEG - 1);
    int b  = bs >> 3;
    float dec = sigmoidf_(decay[e]);
    float ln  = logf(fmaxf(dec, 1e-7f));
    size_t base = (size_t)b * TT * DD + e;
    float sum = 0.0f;
    int t0 = s * SEGLEN;
    #pragma unroll 4
    for (int j = 0; j < SEGLEN; ++j) {
        int t = t0 + j;
        float kv = k[base + (size_t)t * DD] * v[base + (size_t)t * DD];
        float sc = expf((float)t * ln);
        sum += kv / fmaxf(sc, 1e-10f);
    }
    part[idx] = sum;
}

__global__ void timemix_apply(const float* __restrict__ k, const float* __restrict__ v,
                              const float* __restrict__ decay, const float* __restrict__ part,
                              float* __restrict__ state) {
    int idx = blockIdx.x * blockDim.x + threadIdx.x;
    int e  = idx & (DD - 1);
    int bs = idx >> 10;
    int s  = bs & (NSEG - 1);
    int b  = bs >> 3;
    float dec = sigmoidf_(decay[e]);
    float ln  = logf(fmaxf(dec, 1e-7f));
    size_t base = (size_t)b * TT * DD + e;
    float cum = 0.0f;
    for (int s2 = 0; s2 < s; ++s2)
        cum += part[((b * NSEG + s2) << 10) + e];
    int t0 = s * SEGLEN;
    #pragma unroll 4
    for (int j = 0; j < SEGLEN; ++j) {
        int t = t0 + j;
        float kv = k[base + (size_t)t * DD] * v[base + (size_t)t * DD];
        float sc = expf((float)t * ln);
        cum += kv / fmaxf(sc, 1e-10f);
        state[base + (size_t)t * DD] = cum * sc;
    }
}

// ======================= common GEMM macros =======================
#define SWZ(x) ((x) ^ (((x) >> 3) & 0x70))

#define LDSM4(r, addr) \
    asm volatile("ldmatrix.sync.aligned.m8n8.x4.shared.b16 {%0,%1,%2,%3}, [%4];" \
        : "=r"((r)[0]), "=r"((r)[1]), "=r"((r)[2]), "=r"((r)[3]) : "r"(addr))

#define MMA16816(d, a, b0, b1) \
    asm volatile("mma.sync.aligned.m16n8k16.row.col.f32.bf16.bf16.f32 " \
        "{%0,%1,%2,%3}, {%4,%5,%6,%7}, {%8,%9}, {%0,%1,%2,%3};" \
        : "+f"((d)[0]), "+f"((d)[1]), "+f"((d)[2]), "+f"((d)[3]) \
        : "r"((a)[0]), "r"((a)[1]), "r"((a)[2]), "r"((a)[3]), "r"(b0), "r"(b1))

#define CP_ASYNC16(dst, src) \
    asm volatile("{ .reg .u64 g; cvta.to.global.u64 g, %1; cp.async.cg.shared.global [%0], [g], 16; }" \
        :: "r"(dst), "l"(src) : "memory")
#define CP_COMMIT() asm volatile("cp.async.commit_group;" ::: "memory")
#define CP_WAIT2()  asm volatile("cp.async.wait_group 2;" ::: "memory")
#define CP_WAIT1()  asm volatile("cp.async.wait_group 1;" ::: "memory")
#define CP_WAIT0()  asm volatile("cp.async.wait_group 0;" ::: "memory")

__device__ __forceinline__ uint32_t smem_u32(const void* p) {
    uint32_t a;
    asm("{ .reg .u64 t; cvta.to.shared.u64 t, %1; cvt.u32.u64 %0, t; }" : "=r"(a) : "l"(p));
    return a;
}

// ======================= GEMM: CTA 128x128, 1024 thr, 32 warps (4M x 8N), warp 32x16 ======
// Single-barrier 3-stage cp.async pipeline (R12-verified core).
// Fragment layout: LDSM4 -> {n0k0, n0k1, n1k0, n1k1}; B pair for n-sub s = (r[2s], r[2s+1]).
// epi: 0 = store f32, 1 = sigmoid, 2 = residual add,
//      4 = QKV route: c<1024 -> sigmoid->C(r); c<2048 -> D2(k); else D3(v). Row stride DD.
//      5 = interleaved W1/W2 + gate: pair (c,c+1) = (g1_j, g2_j), j=c/2;
//          out = silu(g1)*g2 -> split bf16 scalar to OH/OL at column j, width N/2.
#define PLANE 16384
#define STAGE128 65536   // 4 planes x 128 rows x 128B
#define NST128 3

__global__ void __launch_bounds__(1024)
gemm_hmma(const __nv_bfloat16* __restrict__ Ah, const __nv_bfloat16* __restrict__ Al,
          const __nv_bfloat16* __restrict__ Bh, const __nv_bfloat16* __restrict__ Bl,
          float* __restrict__ C, __nv_bfloat16* __restrict__ OH, __nv_bfloat16* __restrict__ OL,
          float* __restrict__ D2, float* __restrict__ D3,
          int N, int K, int epi) {
    extern __shared__ __align__(1024) char smem[];
    const uint32_t sb = smem_u32(smem);
    const int tid  = threadIdx.x;
    const int lane = tid & 31, wid = tid >> 5;
    const int wm = wid & 3;          // m offset wm*32
    const int wn = wid >> 2;         // 0..7 -> n offset wn*16
    const int bm = blockIdx.y * 128, bn = blockIdx.x * 128;

    // cp.async: 8 threads per 128B row per plane; 1x16B each
    const int lr = tid >> 3;
    const int lq = tid & 7;
    const __nv_bfloat16* psrc[4] = {
        Ah + (size_t)(bm + lr) * K + lq * 8,
        Al + (size_t)(bm + lr) * K + lq * 8,
        Bh + (size_t)(bn + lr) * K + lq * 8,
        Bl + (size_t)(bn + lr) * K + lq * 8
    };
    const uint32_t dsw = SWZ((uint32_t)(lr * 128 + lq * 16));

    const uint32_t aoff0 = (uint32_t)(wm * 32 + (lane & 15)) * 128 + (lane >> 4) * 16;
    const uint32_t boff0 = (uint32_t)(wn * 16 + ((lane >> 4) & 1) * 8 + (lane & 7)) * 128
                         + ((lane >> 3) & 1) * 16;

    float acc[2][2][4];
    #pragma unroll
    for (int mt = 0; mt < 2; ++mt)
        #pragma unroll
        for (int nt = 0; nt < 2; ++nt)
            #pragma unroll
            for (int q = 0; q < 4; ++q) acc[mt][nt][q] = 0.0f;

    const int nch = K >> 6;

    // prologue: chunks 0,1,2 into stages 0,1,2
    #pragma unroll
    for (int s = 0; s < 3; ++s) {
        const uint32_t st = sb + s * STAGE128;
        const int koff = s * 64;
        #pragma unroll
        for (int p = 0; p < 4; ++p)
            CP_ASYNC16(st + p * PLANE + dsw, psrc[p] + koff);
        CP_COMMIT();
    }
    CP_WAIT2();        // chunk 0 arrived
    __syncthreads();

    int buf = 0;
    for (int ch = 0; ch < nch; ++ch) {
        const uint32_t st = sb + buf * STAGE128;
        #pragma unroll
        for (int kk = 0; kk < 4; ++kk) {
            uint32_t ah[2][4], al[2][4], bh[4], bl[4];
            #pragma unroll
            for (int mt = 0; mt < 2; ++mt) {
                uint32_t o = SWZ(aoff0 + mt * 2048 + kk * 32);
                LDSM4(ah[mt], st + o);
                LDSM4(al[mt], st + PLANE + o);
            }
            {
                uint32_t o = SWZ(boff0 + kk * 32);
                LDSM4(bh, st + 2 * PLANE + o);
                LDSM4(bl, st + 3 * PLANE + o);
            }
            #pragma unroll
            for (int mt = 0; mt < 2; ++mt)
                #pragma unroll
                for (int nt = 0; nt < 2; ++nt)
                    MMA16816(acc[mt][nt], ah[mt], bh[nt * 2], bh[nt * 2 + 1]);
            #pragma unroll
            for (int mt = 0; mt < 2; ++mt)
                #pragma unroll
                for (int nt = 0; nt < 2; ++nt)
                    MMA16816(acc[mt][nt], ah[mt], bl[nt * 2], bl[nt * 2 + 1]);
            #pragma unroll
            for (int mt = 0; mt < 2; ++mt)
                #pragma unroll
                for (int nt = 0; nt < 2; ++nt)
                    MMA16816(acc[mt][nt], al[mt], bh[nt * 2], bh[nt * 2 + 1]);
        }
        // wait for chunk ch+1 (issued >= 1 iteration ago)
        if (ch + 2 < nch)      CP_WAIT1();
        else if (ch + 1 < nch) CP_WAIT0();
        __syncthreads();   // (a) all warps done with buf; (b) chunk ch+1 visible
        if (ch + 3 < nch) {
            const int koff = (ch + 3) * 64;
            #pragma unroll
            for (int p = 0; p < 4; ++p)
                CP_ASYNC16(st + p * PLANE + dsw, psrc[p] + koff);
            CP_COMMIT();
        }
        ++buf; if (buf == NST128) buf = 0;
    }

    // epilogue
    const int g  = lane >> 2;
    const int tc = lane & 3;
    #pragma unroll
    for (int mt = 0; mt < 2; ++mt) {
        #pragma unroll
        for (int nt = 0; nt < 2; ++nt) {
            const int r0 = bm + wm * 32 + mt * 16 + g;
            const int c  = bn + wn * 16 + nt * 8 + tc * 2;
            float2 v0 = make_float2(acc[mt][nt][0], acc[mt][nt][1]);
            float2 v1 = make_float2(acc[mt][nt][2], acc[mt][nt][3]);
            if (epi == 5) {
                const int No = N >> 1;
                const int j = c >> 1;
                float o0 = v0.x * sigmoidf_(v0.x) * v0.y;
                float o1 = v1.x * sigmoidf_(v1.x) * v1.y;
                uint16_t h0, l0, h1, l1;
                split1(o0, h0, l0);
                split1(o1, h1, l1);
                ((uint16_t*)OH)[(size_t)r0 * No + j]       = h0;
                ((uint16_t*)OL)[(size_t)r0 * No + j]       = l0;
                ((uint16_t*)OH)[(size_t)(r0 + 8) * No + j] = h1;
                ((uint16_t*)OL)[(size_t)(r0 + 8) * No + j] = l1;
            } else if (epi == 4) {
                const int c2 = c & 1023;
                float* dst;
                if (c < 1024) {
                    v0.x = sigmoidf_(v0.x); v0.y = sigmoidf_(v0.y);
                    v1.x = sigmoidf_(v1.x); v1.y = sigmoidf_(v1.y);
                    dst = C;
                } else if (c < 2048) {
                    dst = D2;
                } else {
                    dst = D3;
                }
                *(float2*)(dst + (size_t)r0 * DD + c2)       = v0;
                *(float2*)(dst + (size_t)(r0 + 8) * DD + c2) = v1;
            } else {
                float* p0 = C + (size_t)r0 * N + c;
                float* p1 = C + (size_t)(r0 + 8) * N + c;
                if (epi == 1) {
                    v0.x = sigmoidf_(v0.x); v0.y = sigmoidf_(v0.y);
                    v1.x = sigmoidf_(v1.x); v1.y = sigmoidf_(v1.y);
                } else if (epi == 2) {
                    float2 c0 = *(const float2*)p0;
                    float2 c1 = *(const float2*)p1;
                    v0.x += c0.x; v0.y += c0.y;
                    v1.x += c1.x; v1.y += c1.y;
                }
                *(float2*)p0 = v0;
                *(float2*)p1 = v1;
            }
        }
    }
}

// ======================= launch =======================
extern "C" void kernel_launch(void* const* d_in, const int* in_sizes, int n_in,
                              void* d_out, int out_size) {
    const int*   x      = (const int*)  d_in[0];
    const float* embed  = (const float*)d_in[1];
    const float* ln_in  = (const float*)d_in[2];
    const float* ln_out = (const float*)d_in[3];
    const float* ln1    = (const float*)d_in[4];
    const float* Wr     = (const float*)d_in[5];
    const float* Wk     = (const float*)d_in[6];
    const float* Wv     = (const float*)d_in[7];
    const float* Wo     = (const float*)d_in[8];
    const float* decay  = (const float*)d_in[9];
    const float* lnx    = (const float*)d_in[10];
    const float* ln2    = (const float*)d_in[11];
    const float* W1     = (const float*)d_in[12];
    const float* W2     = (const float*)d_in[13];
    const float* Wo2    = (const float*)d_in[14];
    float* out = (float*)d_out;

    float *h, *r, *k, *v, *st, *part;
    __nv_bfloat16 *xnh, *xnl, *gh, *gl;
    __nv_bfloat16 *qkvh, *qkvl, *w12h, *w12l, *woh, *wol;
    __nv_bfloat16 *o2h, *o2l, *eh, *el;
    cudaGetSymbolAddress((void**)&h,  g_h);   cudaGetSymbolAddress((void**)&r,  g_r);
    cudaGetSymbolAddress((void**)&k,  g_k);   cudaGetSymbolAddress((void**)&v,  g_v);
    cudaGetSymbolAddress((void**)&st, g_st);  cudaGetSymbolAddress((void**)&part, g_part);
    cudaGetSymbolAddress((void**)&xnh, g_xnh); cudaGetSymbolAddress((void**)&xnl, g_xnl);
    cudaGetSymbolAddress((void**)&gh,  g_gh);  cudaGetSymbolAddress((void**)&gl,  g_gl);
    cudaGetSymbolAddress((void**)&qkvh, g_qkvh); cudaGetSymbolAddress((void**)&qkvl, g_qkvl);
    cudaGetSymbolAddress((void**)&w12h, g_w12h); cudaGetSymbolAddress((void**)&w12l, g_w12l);
    cudaGetSymbolAddress((void**)&woh, g_woh); cudaGetSymbolAddress((void**)&wol, g_wol);
    cudaGetSymbolAddress((void**)&o2h, g_o2h); cudaGetSymbolAddress((void**)&o2l, g_o2l);
    cudaGetSymbolAddress((void**)&eh,  g_eh);  cudaGetSymbolAddress((void**)&el,  g_el);

    const int SMEM = NST128 * STAGE128;   // 196608
    cudaFuncSetAttribute(gemm_hmma, cudaFuncAttributeMaxDynamicSharedMemorySize, SMEM);

    const dim3 blk(256);
    const dim3 gblk(1024);
    const dim3 gQKV(3 * DD / 128, MM / 128);   // 24 x 16 = 384 CTAs
    const dim3 gD(DD / 128, MM / 128);         // 8 x 16
    const dim3 gW12(2 * FF / 128, MM / 128);   // 64 x 16 = 1024 CTAs
    const dim3 gH(VV / 128, MM / 128);         // 250 x 16
    const int TMGRID = (BB * DD * NSEG) / 256;

    // ---- launch order: my index 3 = QKV-GEMM (profiled) ----
    qkv_split_kernel<<<(3*LL*DD*DD)/2048, blk>>>(Wr, Wk, Wv, qkvh, qkvl);   // #0
    embed_rms_kernel<<<MM, blk>>>(x, embed, ln_in, h);                      // #1
    rms_kernel<<<MM, blk>>>(h, nullptr, ln1, xnh, xnl);                     // #2
    gemm_hmma<<<gQKV, gblk, SMEM>>>(xnh, xnl, qkvh, qkvl, r,
                                    nullptr, nullptr, k, v, 3 * DD, DD, 4); // #3 <-- profiled

    // remaining splits
    w12_split_kernel<<<(2*LL*FF*DD)/2048, blk>>>(W1, W2, w12h, w12l);
    split_kernel<<<(LL*DD*DD)/2048, blk>>>(Wo,  woh, wol);
    split_kernel<<<(LL*DD*FF)/2048, blk>>>(Wo2, o2h, o2l);
    split_kernel<<<(VV*DD)/2048,    blk>>>(embed, eh, el);

    for (int l = 0; l < LL; ++l) {
        const size_t oQ  = (size_t)l * 3 * DD * DD;
        const size_t oW  = (size_t)l * 2 * FF * DD;
        const size_t oDD = (size_t)l * DD * DD;
        const size_t oFD = (size_t)l * FF * DD;

        // --- TimeMix ---
        if (l > 0) {
            rms_kernel<<<MM, blk>>>(h, nullptr, ln1 + l * DD, xnh, xnl);
            gemm_hmma<<<gQKV, gblk, SMEM>>>(xnh, xnl, qkvh + oQ, qkvl + oQ, r,
                                            nullptr, nullptr, k, v, 3 * DD, DD, 4);
        }
        timemix_part <<<TMGRID, blk>>>(k, v, decay + l * DD, part);
        timemix_apply<<<TMGRID, blk>>>(k, v, decay + l * DD, part, st);
        rms_kernel<<<MM, blk>>>(st, r, lnx + l * DD, xnh, xnl);
        gemm_hmma<<<gD, gblk, SMEM>>>(xnh, xnl, woh + oDD, wol + oDD, h,
                                      nullptr, nullptr, nullptr, nullptr, DD, DD, 2);

        // --- ChannelMix: single fused W1/W2 GEMM with in-register gate (epi=5) ---
        rms_kernel<<<MM, blk>>>(h, nullptr, ln2 + l * DD, xnh, xnl);
        gemm_hmma<<<gW12, gblk, SMEM>>>(xnh, xnl, w12h + oW, w12l + oW, nullptr,
                                        gh, gl, nullptr, nullptr, 2 * FF, DD, 5);
        gemm_hmma<<<gD, gblk, SMEM>>>(gh, gl, o2h + oFD, o2l + oFD, h,
                                      nullptr, nullptr, nullptr, nullptr, DD, FF, 2);
    }

    // --- tied head ---
    rms_kernel<<<MM, blk>>>(h, nullptr, ln_out, xnh, xnl);
    gemm_hmma<<<gH, gblk, SMEM>>>(xnh, xnl, eh, el, out,
                                  nullptr, nullptr, nullptr, nullptr, VV, DD, 0);
}

// round 17
// speedup vs baseline: 1.4399x; 1.0140x over previous
#include <cuda_runtime.h>
#include <cuda_bf16.h>
#include <stdint.h>
#include <math.h>

#define BB 8
#define TT 256
#define DD 1024
#define LL 12
#define FF 4096
#define VV 32000
#define MM (BB*TT)   // 2048 rows
#define NSEG 8
#define SEGLEN (TT/NSEG)

// ======================= scratch (static device globals; no runtime alloc) =======================
__device__ __align__(256) float g_h [MM*DD];
__device__ __align__(256) float g_r [MM*DD];
__device__ __align__(256) float g_k [MM*DD];
__device__ __align__(256) float g_v [MM*DD];
__device__ __align__(256) float g_st[MM*DD];

__device__ __align__(256) __nv_bfloat16 g_xnh[MM*DD], g_xnl[MM*DD];
__device__ __align__(256) __nv_bfloat16 g_gh [MM*FF], g_gl [MM*FF];

// fused QKV weights: per layer, rows [0,1024)=Wr, [1024,2048)=Wk, [2048,3072)=Wv
__device__ __align__(256) __nv_bfloat16 g_qkvh[LL*3*DD*DD], g_qkvl[LL*3*DD*DD];
// fused W1/W2 weights, interleaved: per layer, row 2j = W1 row j, row 2j+1 = W2 row j
__device__ __align__(256) __nv_bfloat16 g_w12h[LL*2*FF*DD], g_w12l[LL*2*FF*DD];
__device__ __align__(256) __nv_bfloat16 g_woh[LL*DD*DD], g_wol[LL*DD*DD];
__device__ __align__(256) __nv_bfloat16 g_o2h[LL*DD*FF], g_o2l[LL*DD*FF];
__device__ __align__(256) __nv_bfloat16 g_eh [VV*DD],    g_el [VV*DD];

// ======================= split helpers (hi = trunc bf16, lo = rn bf16 of remainder) ==========
__device__ __forceinline__ void split4(float4 v, uint2& hi, uint2& lo) {
    uint32_t h01 = __byte_perm(__float_as_uint(v.x), __float_as_uint(v.y), 0x7632);
    uint32_t h23 = __byte_perm(__float_as_uint(v.z), __float_as_uint(v.w), 0x7632);
    float lx = v.x - __uint_as_float(__float_as_uint(v.x) & 0xffff0000u);
    float ly = v.y - __uint_as_float(__float_as_uint(v.y) & 0xffff0000u);
    float lz = v.z - __uint_as_float(__float_as_uint(v.z) & 0xffff0000u);
    float lw = v.w - __uint_as_float(__float_as_uint(v.w) & 0xffff0000u);
    __nv_bfloat162 p01 = __floats2bfloat162_rn(lx, ly);
    __nv_bfloat162 p23 = __floats2bfloat162_rn(lz, lw);
    hi = make_uint2(h01, h23);
    lo = make_uint2(*reinterpret_cast<uint32_t*>(&p01), *reinterpret_cast<uint32_t*>(&p23));
}

__device__ __forceinline__ void split1(float x, uint16_t& h, uint16_t& l) {
    uint32_t xi = __float_as_uint(x);
    h = (uint16_t)(xi >> 16);
    float lo = x - __uint_as_float(xi & 0xffff0000u);
    __nv_bfloat16 lb = __float2bfloat16_rn(lo);
    l = *reinterpret_cast<uint16_t*>(&lb);
}

// generic split: 2 float4 per thread
__global__ void split_kernel(const float* __restrict__ src, __nv_bfloat16* __restrict__ hi,
                             __nv_bfloat16* __restrict__ lo) {
    size_t i = ((size_t)blockIdx.x * blockDim.x + threadIdx.x) * 2;
    float4 v0 = ((const float4*)src)[i];
    float4 v1 = ((const float4*)src)[i + 1];
    uint2 h0, l0, h1, l1;
    split4(v0, h0, l0);
    split4(v1, h1, l1);
    ((uint2*)hi)[i]     = h0;
    ((uint2*)lo)[i]     = l0;
    ((uint2*)hi)[i + 1] = h1;
    ((uint2*)lo)[i + 1] = l1;
}

// QKV split: packs Wr/Wk/Wv into fused [L][3*DD][DD] layout; 2 float4 per thread
__global__ void qkv_split_kernel(const float* __restrict__ Wr, const float* __restrict__ Wk,
                                 const float* __restrict__ Wv,
                                 __nv_bfloat16* __restrict__ qh, __nv_bfloat16* __restrict__ ql) {
    size_t i = ((size_t)blockIdx.x * blockDim.x + threadIdx.x) * 2;
    #pragma unroll
    for (int e = 0; e < 2; ++e) {
        size_t ii = i + e;                 // dst float4 index
        int dstrow = (int)(ii >> 8);       // DD/4 = 256 float4 per row
        int l   = dstrow / (3 * DD);
        int rem = dstrow - l * 3 * DD;
        int w   = rem >> 10;               // 0=Wr 1=Wk 2=Wv
        int rr  = rem & 1023;
        const float* src = (w == 0) ? Wr : (w == 1) ? Wk : Wv;
        float4 v = ((const float4*)src)[((size_t)l * DD + rr) * 256 + (ii & 255)];
        uint2 h, lo2;
        split4(v, h, lo2);
        ((uint2*)qh)[ii] = h;
        ((uint2*)ql)[ii] = lo2;
    }
}

// W12 split: packs W1/W2 into fused [L][2*FF][DD] interleaved layout; 2 float4 per thread
__global__ void w12_split_kernel(const float* __restrict__ W1, const float* __restrict__ W2,
                                 __nv_bfloat16* __restrict__ qh, __nv_bfloat16* __restrict__ ql) {
    size_t i = ((size_t)blockIdx.x * blockDim.x + threadIdx.x) * 2;
    #pragma unroll
    for (int e = 0; e < 2; ++e) {
        size_t ii = i + e;                 // dst float4 index
        int dstrow = (int)(ii >> 8);       // 256 float4 per 1024-row
        int l   = dstrow / (2 * FF);
        int rem = dstrow - l * 2 * FF;
        int j   = rem >> 1;
        int s   = rem & 1;                 // 0 = W1, 1 = W2
        const float* src = s ? W2 : W1;
        float4 v = ((const float4*)src)[((size_t)l * FF + j) * 256 + (ii & 255)];
        uint2 h, lo2;
        split4(v, h, lo2);
        ((uint2*)qh)[ii] = h;
        ((uint2*)ql)[ii] = lo2;
    }
}

// ======================= aux kernels =======================
__device__ __forceinline__ float block_reduce_sum_256(float val) {
    #pragma unroll
    for (int o = 16; o > 0; o >>= 1) val += __shfl_xor_sync(0xffffffffu, val, o);
    __shared__ float sh[8];
    __shared__ float s_tot;
    int w = threadIdx.x >> 5;
    if ((threadIdx.x & 31) == 0) sh[w] = val;
    __syncthreads();
    if (threadIdx.x < 8) {
        float v2 = sh[threadIdx.x];
        #pragma unroll
        for (int o = 4; o > 0; o >>= 1) v2 += __shfl_xor_sync(0xffu, v2, o);
        if (threadIdx.x == 0) s_tot = v2;
    }
    __syncthreads();
    return s_tot;
}
__device__ __forceinline__ float sigmoidf_(float x) { return 1.0f / (1.0f + expf(-x)); }

// embedding gather + RMSNorm -> f32 h (residual stream)
__global__ void embed_rms_kernel(const int* __restrict__ x, const float* __restrict__ embed,
                                 const float* __restrict__ w, float* __restrict__ out) {
    int row = blockIdx.x;
    int tok = x[row];
    int t = threadIdx.x;
    float4 v = ((const float4*)(embed + (size_t)tok * DD))[t];
    float ss = v.x*v.x + v.y*v.y + v.z*v.z + v.w*v.w;
    float tot = block_reduce_sum_256(ss);
    float s = rsqrtf(tot / (float)DD + 1e-6f);
    float4 wv = ((const float4*)w)[t];
    float4 o = make_float4(v.x*s*wv.x, v.y*s*wv.y, v.z*s*wv.z, v.w*s*wv.w);
    ((float4*)(out + (size_t)row * DD))[t] = o;
}

// RMSNorm (optional elementwise gate) -> bf16 hi/lo planes (feeds GEMM A)
__global__ void rms_kernel(const float* __restrict__ x, const float* __restrict__ gate,
                           const float* __restrict__ w,
                           __nv_bfloat16* __restrict__ oh, __nv_bfloat16* __restrict__ ol) {
    int row = blockIdx.x;
    int t = threadIdx.x;
    float4 v = ((const float4*)(x + (size_t)row * DD))[t];
    if (gate != nullptr) {
        float4 g = ((const float4*)(gate + (size_t)row * DD))[t];
        v.x *= g.x; v.y *= g.y; v.z *= g.z; v.w *= g.w;
    }
    float ss = v.x*v.x + v.y*v.y + v.z*v.z + v.w*v.w;
    float tot = block_reduce_sum_256(ss);
    float s = rsqrtf(tot / (float)DD + 1e-6f);
    float4 wv = ((const float4*)w)[t];
    float4 o = make_float4(v.x*s*wv.x, v.y*s*wv.y, v.z*s*wv.z, v.w*s*wv.w);
    uint2 h, l;
    split4(o, h, l);
    ((uint2*)(oh + (size_t)row * DD))[t] = h;
    ((uint2*)(ol + (size_t)row * DD))[t] = l;
}

// TimeMix recurrence: single kernel, NSEG segments, block-level smem prefix.
// Block = one batch b x 32 channels; thread (s, lc): s = segment, lc = channel lane.
// kv/max(sc) values cached in registers between partial and apply phases.
// Arithmetic order identical to the two-kernel (part+apply) version.
__global__ void timemix_fused(const float* __restrict__ k, const float* __restrict__ v,
                              const float* __restrict__ decay, float* __restrict__ state) {
    __shared__ float sp[NSEG][32];
    int id = blockIdx.x;              // 0..BB*32-1
    int b  = id >> 5;
    int ec = id & 31;                 // channel chunk
    int s  = threadIdx.x >> 5;        // segment 0..7
    int lc = threadIdx.x & 31;
    int e  = ec * 32 + lc;
    float dec = sigmoidf_(decay[e]);
    float ln  = logf(fmaxf(dec, 1e-7f));
    size_t base = (size_t)b * TT * DD + e;
    float kvc[SEGLEN];
    float sum = 0.0f;
    const int t0 = s * SEGLEN;
    #pragma unroll
    for (int j = 0; j < SEGLEN; ++j) {
        int t = t0 + j;
        float kv = k[base + (size_t)t * DD] * v[base + (size_t)t * DD];
        float sc = expf((float)t * ln);
        kvc[j] = kv / fmaxf(sc, 1e-10f);
        sum += kvc[j];
    }
    sp[s][lc] = sum;
    __syncthreads();
    float cum = 0.0f;
    #pragma unroll
    for (int s2 = 0; s2 < NSEG; ++s2)
        if (s2 < s) cum += sp[s2][lc];
    #pragma unroll
    for (int j = 0; j < SEGLEN; ++j) {
        int t = t0 + j;
        cum += kvc[j];
        float sc = expf((float)t * ln);
        state[base + (size_t)t * DD] = cum * sc;
    }
}

// ======================= common GEMM macros =======================
#define SWZ(x) ((x) ^ (((x) >> 3) & 0x70))

#define LDSM4(r, addr) \
    asm volatile("ldmatrix.sync.aligned.m8n8.x4.shared.b16 {%0,%1,%2,%3}, [%4];" \
        : "=r"((r)[0]), "=r"((r)[1]), "=r"((r)[2]), "=r"((r)[3]) : "r"(addr))

#define MMA16816(d, a, b0, b1) \
    asm volatile("mma.sync.aligned.m16n8k16.row.col.f32.bf16.bf16.f32 " \
        "{%0,%1,%2,%3}, {%4,%5,%6,%7}, {%8,%9}, {%0,%1,%2,%3};" \
        : "+f"((d)[0]), "+f"((d)[1]), "+f"((d)[2]), "+f"((d)[3]) \
        : "r"((a)[0]), "r"((a)[1]), "r"((a)[2]), "r"((a)[3]), "r"(b0), "r"(b1))

#define CP_ASYNC16(dst, src) \
    asm volatile("{ .reg .u64 g; cvta.to.global.u64 g, %1; cp.async.cg.shared.global [%0], [g], 16; }" \
        :: "r"(dst), "l"(src) : "memory")
#define CP_COMMIT() asm volatile("cp.async.commit_group;" ::: "memory")
#define CP_WAIT2()  asm volatile("cp.async.wait_group 2;" ::: "memory")
#define CP_WAIT1()  asm volatile("cp.async.wait_group 1;" ::: "memory")
#define CP_WAIT0()  asm volatile("cp.async.wait_group 0;" ::: "memory")

__device__ __forceinline__ uint32_t smem_u32(const void* p) {
    uint32_t a;
    asm("{ .reg .u64 t; cvta.to.shared.u64 t, %1; cvt.u32.u64 %0, t; }" : "=r"(a) : "l"(p));
    return a;
}

// ======================= GEMM: CTA 128x128, 1024 thr, 32 warps (4M x 8N), warp 32x16 ======
// Single-barrier 3-stage cp.async pipeline. Per-warp kk stagger: warps on the same SMSP
// (same wid&3) start at different kk -> LDSM and MMA convoys de-phase across warps.
// Fragment layout: LDSM4 -> {n0k0, n0k1, n1k0, n1k1}; B pair for n-sub s = (r[2s], r[2s+1]).
// epi: 0 = store f32, 1 = sigmoid, 2 = residual add,
//      4 = QKV route: c<1024 -> sigmoid->C(r); c<2048 -> D2(k); else D3(v). Row stride DD.
//      5 = interleaved W1/W2 + gate: pair (c,c+1) = (g1_j, g2_j), j=c/2;
//          out = silu(g1)*g2 -> split bf16 scalar to OH/OL at column j, width N/2.
#define PLANE 16384
#define STAGE128 65536   // 4 planes x 128 rows x 128B
#define NST128 3

__global__ void __launch_bounds__(1024)
gemm_hmma(const __nv_bfloat16* __restrict__ Ah, const __nv_bfloat16* __restrict__ Al,
          const __nv_bfloat16* __restrict__ Bh, const __nv_bfloat16* __restrict__ Bl,
          float* __restrict__ C, __nv_bfloat16* __restrict__ OH, __nv_bfloat16* __restrict__ OL,
          float* __restrict__ D2, float* __restrict__ D3,
          int N, int K, int epi) {
    extern __shared__ __align__(1024) char smem[];
    const uint32_t sb = smem_u32(smem);
    const int tid  = threadIdx.x;
    const int lane = tid & 31, wid = tid >> 5;
    const int wm = wid & 3;          // m offset wm*32
    const int wn = wid >> 2;         // 0..7 -> n offset wn*16
    const int kks = wn & 3;          // per-warp kk start offset (same-SMSP warps differ)
    const int bm = blockIdx.y * 128, bn = blockIdx.x * 128;

    // cp.async: 8 threads per 128B row per plane; 1x16B each
    const int lr = tid >> 3;
    const int lq = tid & 7;
    const __nv_bfloat16* psrc[4] = {
        Ah + (size_t)(bm + lr) * K + lq * 8,
        Al + (size_t)(bm + lr) * K + lq * 8,
        Bh + (size_t)(bn + lr) * K + lq * 8,
        Bl + (size_t)(bn + lr) * K + lq * 8
    };
    const uint32_t dsw = SWZ((uint32_t)(lr * 128 + lq * 16));

    const uint32_t aoff0 = (uint32_t)(wm * 32 + (lane & 15)) * 128 + (lane >> 4) * 16;
    const uint32_t boff0 = (uint32_t)(wn * 16 + ((lane >> 4) & 1) * 8 + (lane & 7)) * 128
                         + ((lane >> 3) & 1) * 16;

    float acc[2][2][4];
    #pragma unroll
    for (int mt = 0; mt < 2; ++mt)
        #pragma unroll
        for (int nt = 0; nt < 2; ++nt)
            #pragma unroll
            for (int q = 0; q < 4; ++q) acc[mt][nt][q] = 0.0f;

    const int nch = K >> 6;

    // prologue: chunks 0,1,2 into stages 0,1,2
    #pragma unroll
    for (int s = 0; s < 3; ++s) {
        const uint32_t st = sb + s * STAGE128;
        const int koff = s * 64;
        #pragma unroll
        for (int p = 0; p < 4; ++p)
            CP_ASYNC16(st + p * PLANE + dsw, psrc[p] + koff);
        CP_COMMIT();
    }
    CP_WAIT2();        // chunk 0 arrived
    __syncthreads();

    int buf = 0;
    for (int ch = 0; ch < nch; ++ch) {
        const uint32_t st = sb + buf * STAGE128;
        #pragma unroll
        for (int kk0 = 0; kk0 < 4; ++kk0) {
            const int kk = (kk0 + kks) & 3;
            uint32_t ah[2][4], al[2][4], bh[4], bl[4];
            #pragma unroll
            for (int mt = 0; mt < 2; ++mt) {
                uint32_t o = SWZ(aoff0 + mt * 2048 + kk * 32);
                LDSM4(ah[mt], st + o);
                LDSM4(al[mt], st + PLANE + o);
            }
            {
                uint32_t o = SWZ(boff0 + kk * 32);
                LDSM4(bh, st + 2 * PLANE + o);
                LDSM4(bl, st + 3 * PLANE + o);
            }
            #pragma unroll
            for (int mt = 0; mt < 2; ++mt)
                #pragma unroll
                for (int nt = 0; nt < 2; ++nt)
                    MMA16816(acc[mt][nt], ah[mt], bh[nt * 2], bh[nt * 2 + 1]);
            #pragma unroll
            for (int mt = 0; mt < 2; ++mt)
                #pragma unroll
                for (int nt = 0; nt < 2; ++nt)
                    MMA16816(acc[mt][nt], ah[mt], bl[nt * 2], bl[nt * 2 + 1]);
            #pragma unroll
            for (int mt = 0; mt < 2; ++mt)
                #pragma unroll
                for (int nt = 0; nt < 2; ++nt)
                    MMA16816(acc[mt][nt], al[mt], bh[nt * 2], bh[nt * 2 + 1]);
        }
        // wait for chunk ch+1 (issued >= 1 iteration ago)
        if (ch + 2 < nch)      CP_WAIT1();
        else if (ch + 1 < nch) CP_WAIT0();
        __syncthreads();   // (a) all warps done with buf; (b) chunk ch+1 visible
        if (ch + 3 < nch) {
            const int koff = (ch + 3) * 64;
            #pragma unroll
            for (int p = 0; p < 4; ++p)
                CP_ASYNC16(st + p * PLANE + dsw, psrc[p] + koff);
            CP_COMMIT();
        }
        ++buf; if (buf == NST128) buf = 0;
    }

    // epilogue
    const int g  = lane >> 2;
    const int tc = lane & 3;
    #pragma unroll
    for (int mt = 0; mt < 2; ++mt) {
        #pragma unroll
        for (int nt = 0; nt < 2; ++nt) {
            const int r0 = bm + wm * 32 + mt * 16 + g;
            const int c  = bn + wn * 16 + nt * 8 + tc * 2;
            float2 v0 = make_float2(acc[mt][nt][0], acc[mt][nt][1]);
            float2 v1 = make_float2(acc[mt][nt][2], acc[mt][nt][3]);
            if (epi == 5) {
                const int No = N >> 1;
                const int j = c >> 1;
                float o0 = v0.x * sigmoidf_(v0.x) * v0.y;
                float o1 = v1.x * sigmoidf_(v1.x) * v1.y;
                uint16_t h0, l0, h1, l1;
                split1(o0, h0, l0);
                split1(o1, h1, l1);
                ((uint16_t*)OH)[(size_t)r0 * No + j]       = h0;
                ((uint16_t*)OL)[(size_t)r0 * No + j]       = l0;
                ((uint16_t*)OH)[(size_t)(r0 + 8) * No + j] = h1;
                ((uint16_t*)OL)[(size_t)(r0 + 8) * No + j] = l1;
            } else if (epi == 4) {
                const int c2 = c & 1023;
                float* dst;
                if (c < 1024) {
                    v0.x = sigmoidf_(v0.x); v0.y = sigmoidf_(v0.y);
                    v1.x = sigmoidf_(v1.x); v1.y = sigmoidf_(v1.y);
                    dst = C;
                } else if (c < 2048) {
                    dst = D2;
                } else {
                    dst = D3;
                }
                *(float2*)(dst + (size_t)r0 * DD + c2)       = v0;
                *(float2*)(dst + (size_t)(r0 + 8) * DD + c2) = v1;
            } else {
                float* p0 = C + (size_t)r0 * N + c;
                float* p1 = C + (size_t)(r0 + 8) * N + c;
                if (epi == 1) {
                    v0.x = sigmoidf_(v0.x); v0.y = sigmoidf_(v0.y);
                    v1.x = sigmoidf_(v1.x); v1.y = sigmoidf_(v1.y);
                } else if (epi == 2) {
                    float2 c0 = *(const float2*)p0;
                    float2 c1 = *(const float2*)p1;
                    v0.x += c0.x; v0.y += c0.y;
                    v1.x += c1.x; v1.y += c1.y;
                }
                *(float2*)p0 = v0;
                *(float2*)p1 = v1;
            }
        }
    }
}

// ======================= launch =======================
extern "C" void kernel_launch(void* const* d_in, const int* in_sizes, int n_in,
                              void* d_out, int out_size) {
    const int*   x      = (const int*)  d_in[0];
    const float* embed  = (const float*)d_in[1];
    const float* ln_in  = (const float*)d_in[2];
    const float* ln_out = (const float*)d_in[3];
    const float* ln1    = (const float*)d_in[4];
    const float* Wr     = (const float*)d_in[5];
    const float* Wk     = (const float*)d_in[6];
    const float* Wv     = (const float*)d_in[7];
    const float* Wo     = (const float*)d_in[8];
    const float* decay  = (const float*)d_in[9];
    const float* lnx    = (const float*)d_in[10];
    const float* ln2    = (const float*)d_in[11];
    const float* W1     = (const float*)d_in[12];
    const float* W2     = (const float*)d_in[13];
    const float* Wo2    = (const float*)d_in[14];
    float* out = (float*)d_out;

    float *h, *r, *k, *v, *st;
    __nv_bfloat16 *xnh, *xnl, *gh, *gl;
    __nv_bfloat16 *qkvh, *qkvl, *w12h, *w12l, *woh, *wol;
    __nv_bfloat16 *o2h, *o2l, *eh, *el;
    cudaGetSymbolAddress((void**)&h,  g_h);   cudaGetSymbolAddress((void**)&r,  g_r);
    cudaGetSymbolAddress((void**)&k,  g_k);   cudaGetSymbolAddress((void**)&v,  g_v);
    cudaGetSymbolAddress((void**)&st, g_st);
    cudaGetSymbolAddress((void**)&xnh, g_xnh); cudaGetSymbolAddress((void**)&xnl, g_xnl);
    cudaGetSymbolAddress((void**)&gh,  g_gh);  cudaGetSymbolAddress((void**)&gl,  g_gl);
    cudaGetSymbolAddress((void**)&qkvh, g_qkvh); cudaGetSymbolAddress((void**)&qkvl, g_qkvl);
    cudaGetSymbolAddress((void**)&w12h, g_w12h); cudaGetSymbolAddress((void**)&w12l, g_w12l);
    cudaGetSymbolAddress((void**)&woh, g_woh); cudaGetSymbolAddress((void**)&wol, g_wol);
    cudaGetSymbolAddress((void**)&o2h, g_o2h); cudaGetSymbolAddress((void**)&o2l, g_o2l);
    cudaGetSymbolAddress((void**)&eh,  g_eh);  cudaGetSymbolAddress((void**)&el,  g_el);

    const int SMEM = NST128 * STAGE128;   // 196608
    cudaFuncSetAttribute(gemm_hmma, cudaFuncAttributeMaxDynamicSharedMemorySize, SMEM);

    const dim3 blk(256);
    const dim3 gblk(1024);
    const dim3 gQKV(3 * DD / 128, MM / 128);   // 24 x 16 = 384 CTAs
    const dim3 gD(DD / 128, MM / 128);         // 8 x 16
    const dim3 gW12(2 * FF / 128, MM / 128);   // 64 x 16 = 1024 CTAs
    const dim3 gH(VV / 128, MM / 128);         // 250 x 16
    const int TMGRID = BB * 32;                // 256 blocks

    // ---- launch order: my index 3 = QKV-GEMM (profiled) ----
    qkv_split_kernel<<<(3*LL*DD*DD)/2048, blk>>>(Wr, Wk, Wv, qkvh, qkvl);   // #0
    embed_rms_kernel<<<MM, blk>>>(x, embed, ln_in, h);                      // #1
    rms_kernel<<<MM, blk>>>(h, nullptr, ln1, xnh, xnl);                     // #2
    gemm_hmma<<<gQKV, gblk, SMEM>>>(xnh, xnl, qkvh, qkvl, r,
                                    nullptr, nullptr, k, v, 3 * DD, DD, 4); // #3 <-- profiled

    // remaining splits
    w12_split_kernel<<<(2*LL*FF*DD)/2048, blk>>>(W1, W2, w12h, w12l);
    split_kernel<<<(LL*DD*DD)/2048, blk>>>(Wo,  woh, wol);
    split_kernel<<<(LL*DD*FF)/2048, blk>>>(Wo2, o2h, o2l);
    split_kernel<<<(VV*DD)/2048,    blk>>>(embed, eh, el);

    for (int l = 0; l < LL; ++l) {
        const size_t oQ  = (size_t)l * 3 * DD * DD;
        const size_t oW  = (size_t)l * 2 * FF * DD;
        const size_t oDD = (size_t)l * DD * DD;
        const size_t oFD = (size_t)l * FF * DD;

        // --- TimeMix ---
        if (l > 0) {
            rms_kernel<<<MM, blk>>>(h, nullptr, ln1 + l * DD, xnh, xnl);
            gemm_hmma<<<gQKV, gblk, SMEM>>>(xnh, xnl, qkvh + oQ, qkvl + oQ, r,
                                            nullptr, nullptr, k, v, 3 * DD, DD, 4);
        }
        timemix_fused<<<TMGRID, blk>>>(k, v, decay + l * DD, st);
        rms_kernel<<<MM, blk>>>(st, r, lnx + l * DD, xnh, xnl);
        gemm_hmma<<<gD, gblk, SMEM>>>(xnh, xnl, woh + oDD, wol + oDD, h,
                                      nullptr, nullptr, nullptr, nullptr, DD, DD, 2);

        // --- ChannelMix: single fused W1/W2 GEMM with in-register gate (epi=5) ---
        rms_kernel<<<MM, blk>>>(h, nullptr, ln2 + l * DD, xnh, xnl);
        gemm_hmma<<<gW12, gblk, SMEM>>>(xnh, xnl, w12h + oW, w12l + oW, nullptr,
                                        gh, gl, nullptr, nullptr, 2 * FF, DD, 5);
        gemm_hmma<<<gD, gblk, SMEM>>>(gh, gl, o2h + oFD, o2l + oFD, h,
                                      nullptr, nullptr, nullptr, nullptr, DD, FF, 2);
    }

    // --- tied head ---
    rms_kernel<<<MM, blk>>>(h, nullptr, ln_out, xnh, xnl);
    gemm_hmma<<<gH, gblk, SMEM>>>(xnh, xnl, eh, el, out,
                                  nullptr, nullptr, nullptr, nullptr, VV, DD, 0);
}